// round 8
// baseline (speedup 1.0000x reference)
#include <cuda_runtime.h>
#include <cuda_fp16.h>
#include <math.h>
#include <stdint.h>

// Problem constants
#define B_  4
#define T_  2048
#define C_  1024
#define C3_ 3072
#define H_  16
#define HS_ 64
#define FF_ 4096
#define M_  (B_*T_)     // 8192 rows
#define EPS_ 1e-5f

// ---------------- scratch (no dynamic alloc allowed) ----------------
__device__ __half g_h   [M_*C_];    // LN output (half)
__device__ float  g_qkv [M_*C3_];   // fused q|k|v fp32 (tf32-rounded) for attention
__device__ __half g_o   [M_*C_];    // attention output (half)
__device__ float  g_x1  [M_*C_];    // x + attn_out @ Wproj + bproj (fp32)
__device__ __half g_ff  [M_*FF_];   // relu(h2 @ W1 + b1) (half)
__device__ __half g_wqkv[C3_*C_];   // repacked+transposed [3C, C] qkv weight (half)
__device__ __half g_wp  [C_*C_];    // transposed Wproj [N,K] (half)
__device__ __half g_w1  [FF_*C_];   // transposed W1 [4096,1024] (half)
__device__ __half g_w2  [C_*FF_];   // transposed W2 [1024,4096] (half)

__device__ __forceinline__ uint32_t f2tf32(float f) {
    uint32_t u;
    asm("cvt.rna.tf32.f32 %0, %1;" : "=r"(u) : "f"(f));
    return u;
}
__device__ __forceinline__ float roundtf(float f) {
    return __uint_as_float(f2tf32(f));
}

// tf32 mma (attention)
__device__ __forceinline__ void mma_tf32(float* c, const uint32_t* a, const uint32_t* b) {
    asm volatile("mma.sync.aligned.m16n8k8.row.col.f32.tf32.tf32.f32 "
        "{%0,%1,%2,%3}, {%4,%5,%6,%7}, {%8,%9}, {%0,%1,%2,%3};"
        : "+f"(c[0]), "+f"(c[1]), "+f"(c[2]), "+f"(c[3])
        : "r"(a[0]), "r"(a[1]), "r"(a[2]), "r"(a[3]), "r"(b[0]), "r"(b[1]));
}
// fp16 mma (GEMMs)
__device__ __forceinline__ void mma_fp16(float* c, const uint32_t* a, const uint32_t* b) {
    asm volatile("mma.sync.aligned.m16n8k16.row.col.f32.f16.f16.f32 "
        "{%0,%1,%2,%3}, {%4,%5,%6,%7}, {%8,%9}, {%0,%1,%2,%3};"
        : "+f"(c[0]), "+f"(c[1]), "+f"(c[2]), "+f"(c[3])
        : "r"(a[0]), "r"(a[1]), "r"(a[2]), "r"(a[3]), "r"(b[0]), "r"(b[1]));
}
__device__ __forceinline__ uint32_t smem_u32(const void* p) {
    return (uint32_t)__cvta_generic_to_shared(p);
}

// ---------------- LayerNorm: fp32 in, half out ----------------
__global__ __launch_bounds__(256) void ln_kernel(const float* __restrict__ x,
                                                 const float* __restrict__ g,
                                                 const float* __restrict__ b,
                                                 __half* __restrict__ y)
{
    int row = blockIdx.x;
    const float* xr = x + (size_t)row * C_;
    __half* yr = y + (size_t)row * C_;
    int tid = threadIdx.x;

    float s = 0.f, s2 = 0.f;
    #pragma unroll
    for (int i = tid; i < C_; i += 256) {
        float v = xr[i];
        s += v; s2 += v * v;
    }
    __shared__ float rs[256], rs2[256];
    rs[tid] = s; rs2[tid] = s2;
    __syncthreads();
    for (int off = 128; off > 0; off >>= 1) {
        if (tid < off) { rs[tid] += rs[tid+off]; rs2[tid] += rs2[tid+off]; }
        __syncthreads();
    }
    float mean = rs[0] * (1.0f / C_);
    float var  = rs2[0] * (1.0f / C_) - mean * mean;
    float rstd = rsqrtf(var + EPS_);
    #pragma unroll
    for (int i = tid; i < C_; i += 256) {
        yr[i] = __float2half_rn((xr[i] - mean) * rstd * g[i] + b[i]);
    }
}

// ---------------- repack [H,C,HS]x3 -> [3C, C] half ----------------
__global__ void repack_qkv3T(const float* __restrict__ Wq,
                             const float* __restrict__ Wk,
                             const float* __restrict__ Wv,
                             __half* __restrict__ Wt)
{
    int idx = blockIdx.x * 256 + threadIdx.x;   // idx = n*C + c
    if (idx < C3_*C_) {
        int n = idx >> 10;
        int c = idx & (C_ - 1);
        int sec = n >> 10;
        int nn = n & (C_ - 1);
        int h = nn >> 6;
        int d = nn & (HS_ - 1);
        const float* W = (sec == 0) ? Wq : (sec == 1) ? Wk : Wv;
        Wt[idx] = __float2half_rn(W[(size_t)h * C_ * HS_ + (size_t)c * HS_ + d]);
    }
}

// ---------------- transpose to half: src [R, Cc] fp32 -> dst [Cc, R] half -------
__global__ void transpose_h(const float* __restrict__ S, __half* __restrict__ D,
                            int R, int Cc)
{
    __shared__ float t[32][33];
    int bx = blockIdx.x * 32, by = blockIdx.y * 32;
    int x = threadIdx.x, y = threadIdx.y;
    #pragma unroll
    for (int i = 0; i < 32; i += 8)
        t[y + i][x] = S[(size_t)(by + y + i) * Cc + bx + x];
    __syncthreads();
    #pragma unroll
    for (int i = 0; i < 32; i += 8)
        D[(size_t)(bx + y + i) * R + by + x] = __float2half_rn(t[x][y + i]);
}

// ---------------- fp16 mma.sync GEMM ----------------
// C[M,N] = A[M,K] @ Bt[N,K]^T  (+bias)(+res)(relu)
// out_mode: 0 = fp32, 1 = fp32 tf32-rounded, 2 = half
// 256x128 CTA tile, BK=32 halves, 8 warps at 64x64 each, 3-stage cp.async.
// Row stride 40 halves -> frag b32 loads hit banks 20g+tg: conflict-free.
#define HSTR 40
#define HG_STAGE ((256+128)*HSTR)      // halves per stage = 15360
#define HG_SMEM  (3*HG_STAGE*2)        // 92160 bytes

__global__ __launch_bounds__(256, 1) void gemm_fp16(const __half* __restrict__ A,
                                                    const __half* __restrict__ Bt,
                                                    void* __restrict__ Cm,
                                                    int Mn, int Nn, int Kn,
                                                    const float* __restrict__ bias,
                                                    const float* __restrict__ res,
                                                    int relu, int out_mode)
{
    extern __shared__ __half smh[];
    const int tid = threadIdx.x;
    const int wid = tid >> 5, lane = tid & 31;
    const int g = lane >> 2, tg = lane & 3;
    const int warp_m = wid >> 1;       // 0..3  (64 rows each)
    const int warp_n = wid & 1;        // 0..1  (64 cols each)
    const int bm = blockIdx.x * 256;
    const int bn = blockIdx.y * 128;

    float acc[4][8][4];
    #pragma unroll
    for (int mi = 0; mi < 4; mi++)
        #pragma unroll
        for (int ni = 0; ni < 8; ni++)
            #pragma unroll
            for (int r = 0; r < 4; r++) acc[mi][ni][r] = 0.f;

    auto fill = [&](int s, int kt) {
        const int k0 = kt << 5;
        __half* As = smh + s * HG_STAGE;
        __half* Bs = As + 256 * HSTR;
        #pragma unroll
        for (int i = 0; i < 4; i++) {               // A: 1024 chunks of 16B
            int idx = tid + (i << 8);
            int r = idx >> 2, c8 = (idx & 3) << 3;
            uint32_t da = smem_u32(As + r * HSTR + c8);
            asm volatile("cp.async.cg.shared.global [%0], [%1], 16;"
                         :: "r"(da), "l"(A + (size_t)(bm + r) * Kn + k0 + c8));
        }
        #pragma unroll
        for (int i = 0; i < 2; i++) {               // B: 512 chunks of 16B
            int idx = tid + (i << 8);
            int r = idx >> 2, c8 = (idx & 3) << 3;
            uint32_t db = smem_u32(Bs + r * HSTR + c8);
            asm volatile("cp.async.cg.shared.global [%0], [%1], 16;"
                         :: "r"(db), "l"(Bt + (size_t)(bn + r) * Kn + k0 + c8));
        }
        asm volatile("cp.async.commit_group;");
    };

    const int KT = Kn >> 5;
    fill(0, 0);
    fill(1, 1);

    for (int kt = 0; kt < KT; kt++) {
        if (kt < KT - 1) asm volatile("cp.async.wait_group 1;");
        else             asm volatile("cp.async.wait_group 0;");
        __syncthreads();
        if (kt + 2 < KT) fill((kt + 2) % 3, kt + 2);

        const __half* As = smh + (kt % 3) * HG_STAGE;
        const __half* Bs = As + 256 * HSTR;

        #pragma unroll
        for (int ks = 0; ks < 2; ks++) {
            const int kb = ks * 16 + 2 * tg;
            uint32_t af[4][4], bf[8][2];
            #pragma unroll
            for (int mi = 0; mi < 4; mi++) {
                const __half* ap = As + (warp_m * 64 + mi * 16 + g) * HSTR + kb;
                af[mi][0] = *(const uint32_t*)ap;
                af[mi][1] = *(const uint32_t*)(ap + 8 * HSTR);
                af[mi][2] = *(const uint32_t*)(ap + 8);
                af[mi][3] = *(const uint32_t*)(ap + 8 * HSTR + 8);
            }
            #pragma unroll
            for (int ni = 0; ni < 8; ni++) {
                const __half* bp = Bs + (warp_n * 64 + ni * 8 + g) * HSTR + kb;
                bf[ni][0] = *(const uint32_t*)bp;
                bf[ni][1] = *(const uint32_t*)(bp + 8);
            }
            #pragma unroll
            for (int mi = 0; mi < 4; mi++)
                #pragma unroll
                for (int ni = 0; ni < 8; ni++)
                    mma_fp16(acc[mi][ni], af[mi], bf[ni]);
        }
    }

    // epilogue: c0/c1 = row g cols 2tg,2tg+1; c2/c3 at row g+8
    #pragma unroll
    for (int mi = 0; mi < 4; mi++) {
        #pragma unroll
        for (int ni = 0; ni < 8; ni++) {
            int row0 = bm + warp_m * 64 + mi * 16 + g;
            int col  = bn + warp_n * 64 + ni * 8 + tg * 2;
            float bx = 0.f, by = 0.f;
            if (bias) { bx = bias[col]; by = bias[col + 1]; }
            #pragma unroll
            for (int half_ = 0; half_ < 2; half_++) {
                int row = row0 + half_ * 8;
                float v0 = acc[mi][ni][half_ * 2 + 0] + bx;
                float v1 = acc[mi][ni][half_ * 2 + 1] + by;
                if (res) {
                    const float* rp = res + (size_t)row * Nn + col;
                    v0 += rp[0]; v1 += rp[1];
                }
                if (relu) { v0 = fmaxf(v0, 0.f); v1 = fmaxf(v1, 0.f); }
                if (out_mode == 2) {
                    __half2 hv = __floats2half2_rn(v0, v1);
                    *(__half2*)((__half*)Cm + (size_t)row * Nn + col) = hv;
                } else {
                    if (out_mode == 1) { v0 = roundtf(v0); v1 = roundtf(v1); }
                    *(float2*)((float*)Cm + (size_t)row * Nn + col) = make_float2(v0, v1);
                }
            }
        }
    }
}

// ---------------- tensor-core flash attention (tf32, register-resident P) -------
// fp32 qkv in, half out. 128 queries/block, 8 warps, 64-key tiles.
#define KSTR 68
#define VSTR 68
#define PSTR 68
#define ATTN_SMEM ((2*64*KSTR + 2*64*VSTR + 128*PSTR)*4)   // 104448

__global__ __launch_bounds__(256, 2) void attn_tc(const float* __restrict__ qkv,
                                                  __half* __restrict__ o)
{
    extern __shared__ float sm[];
    float* Ks = sm;                      // 2 stages of 64 x KSTR
    float* Vs = sm + 2*64*KSTR;          // 2 stages of 64 x VSTR
    float* Ps = Vs + 2*64*VSTR;          // 128 x PSTR (Q staging, pre-scaled)

    const int tid = threadIdx.x, wid = tid >> 5, lane = tid & 31;
    const int g = lane >> 2, tg = lane & 3;
    const int qt0 = blockIdx.x * 128;
    const int h = blockIdx.y, b = blockIdx.z;

    const float* qbase = qkv + (size_t)(b * T_ + qt0) * C3_ + h * HS_;
    const float* kbase = qkv + (size_t)b * T_ * C3_ + C_  + h * HS_;
    const float* vbase = qkv + (size_t)b * T_ * C3_ + 2*C_ + h * HS_;

    // stage Q tile (128x64), pre-scaled by 1/8 (exact in tf32)
    {
        int r = tid >> 1, c = (tid & 1) * 32;
        #pragma unroll
        for (int cc = 0; cc < 8; cc++) {
            float4 v = *(const float4*)(qbase + (size_t)r * C3_ + c + cc * 4);
            v.x *= 0.125f; v.y *= 0.125f; v.z *= 0.125f; v.w *= 0.125f;
            *(float4*)&Ps[r * PSTR + c + cc * 4] = v;
        }
    }

    float mrow0 = -INFINITY, mrow1 = -INFINITY, lrow0 = 0.f, lrow1 = 0.f;
    float oacc[8][4];
    #pragma unroll
    for (int j = 0; j < 8; j++)
        #pragma unroll
        for (int r = 0; r < 4; r++) oacc[j][r] = 0.f;

    const int m0 = wid * 16;
    const int r0 = qt0 + m0 + g;
    const int my_max = qt0 + m0 + 15;
    const int ntiles = (qt0 + 128) >> 6;

    auto loadKV = [&](int s, int s0) {
        const float* kp = kbase + (size_t)s0 * C3_;
        const float* vp = vbase + (size_t)s0 * C3_;
        float* Kd = Ks + s * 64 * KSTR;
        float* Vd = Vs + s * 64 * VSTR;
        #pragma unroll
        for (int i = 0; i < 4; i++) {
            int idx = tid + i * 256;
            int r = idx >> 4, c = (idx & 15) * 4;
            uint32_t dk = smem_u32(Kd + r * KSTR + c);
            asm volatile("cp.async.cg.shared.global [%0], [%1], 16;"
                         :: "r"(dk), "l"(kp + (size_t)r * C3_ + c));
            uint32_t dv = smem_u32(Vd + r * VSTR + c);
            asm volatile("cp.async.cg.shared.global [%0], [%1], 16;"
                         :: "r"(dv), "l"(vp + (size_t)r * C3_ + c));
        }
        asm volatile("cp.async.commit_group;");
    };

    loadKV(0, 0);
    __syncthreads();   // Q staging visible (and ordered before first compute)

    for (int t = 0; t < ntiles; t++) {
        const int s0 = t * 64;
        asm volatile("cp.async.wait_group 0;");
        __syncthreads();
        if (t + 1 < ntiles) loadKV((t + 1) & 1, s0 + 64);

        if (s0 <= my_max) {
            const float* Kt = Ks + (t & 1) * 64 * KSTR;
            const float* Vt = Vs + (t & 1) * 64 * VSTR;

            // S = (Q/8) @ K^T  (k-lane remap sigma(tg)=2tg)
            float sf[8][4];
            #pragma unroll
            for (int j = 0; j < 8; j++)
                #pragma unroll
                for (int r = 0; r < 4; r++) sf[j][r] = 0.f;
            #pragma unroll
            for (int k = 0; k < 8; k++) {
                const int kb = k * 8 + 2 * tg;
                uint32_t aq[4];
                {
                    float2 lo = *(const float2*)(Ps + (m0 + g) * PSTR + kb);
                    float2 hi = *(const float2*)(Ps + (m0 + g + 8) * PSTR + kb);
                    aq[0] = __float_as_uint(lo.x);
                    aq[1] = __float_as_uint(hi.x);
                    aq[2] = __float_as_uint(lo.y);
                    aq[3] = __float_as_uint(hi.y);
                }
                #pragma unroll
                for (int j = 0; j < 8; j++) {
                    float2 kv = *(const float2*)(Kt + (j * 8 + g) * KSTR + kb);
                    uint32_t bk[2] = { __float_as_uint(kv.x), __float_as_uint(kv.y) };
                    mma_tf32(sf[j], aq, bk);
                }
            }

            // causal mask + online softmax
            float mx0 = -INFINITY, mx1 = -INFINITY;
            #pragma unroll
            for (int j = 0; j < 8; j++) {
                int c0 = s0 + j * 8 + 2 * tg, c1 = c0 + 1;
                if (c0 > r0)     sf[j][0] = -INFINITY;
                if (c1 > r0)     sf[j][1] = -INFINITY;
                if (c0 > r0 + 8) sf[j][2] = -INFINITY;
                if (c1 > r0 + 8) sf[j][3] = -INFINITY;
                mx0 = fmaxf(mx0, fmaxf(sf[j][0], sf[j][1]));
                mx1 = fmaxf(mx1, fmaxf(sf[j][2], sf[j][3]));
            }
            mx0 = fmaxf(mx0, __shfl_xor_sync(0xffffffffu, mx0, 1));
            mx0 = fmaxf(mx0, __shfl_xor_sync(0xffffffffu, mx0, 2));
            mx1 = fmaxf(mx1, __shfl_xor_sync(0xffffffffu, mx1, 1));
            mx1 = fmaxf(mx1, __shfl_xor_sync(0xffffffffu, mx1, 2));

            float mn0 = fmaxf(mrow0, mx0), mn1 = fmaxf(mrow1, mx1);
            float corr0 = __expf(mrow0 - mn0), corr1 = __expf(mrow1 - mn1);
            float sum0 = 0.f, sum1 = 0.f;
            #pragma unroll
            for (int j = 0; j < 8; j++) {
                sf[j][0] = __expf(sf[j][0] - mn0);
                sf[j][1] = __expf(sf[j][1] - mn0);
                sf[j][2] = __expf(sf[j][2] - mn1);
                sf[j][3] = __expf(sf[j][3] - mn1);
                sum0 += sf[j][0] + sf[j][1];
                sum1 += sf[j][2] + sf[j][3];
            }
            sum0 += __shfl_xor_sync(0xffffffffu, sum0, 1);
            sum0 += __shfl_xor_sync(0xffffffffu, sum0, 2);
            sum1 += __shfl_xor_sync(0xffffffffu, sum1, 1);
            sum1 += __shfl_xor_sync(0xffffffffu, sum1, 2);
            lrow0 = lrow0 * corr0 + sum0;
            lrow1 = lrow1 * corr1 + sum1;
            mrow0 = mn0; mrow1 = mn1;
            #pragma unroll
            for (int j = 0; j < 8; j++) {
                oacc[j][0] *= corr0; oacc[j][1] *= corr0;
                oacc[j][2] *= corr1; oacc[j][3] *= corr1;
            }

            // O += P @ V : A-frag = score C-frag (in-register, tf32-rounded)
            #pragma unroll
            for (int kk = 0; kk < 8; kk++) {
                uint32_t ap[4] = { f2tf32(sf[kk][0]), f2tf32(sf[kk][2]),
                                   f2tf32(sf[kk][1]), f2tf32(sf[kk][3]) };
                const float* v0p = Vt + (kk * 8 + 2 * tg) * VSTR + g;
                #pragma unroll
                for (int jn = 0; jn < 8; jn++) {
                    uint32_t bv[2] = { __float_as_uint(v0p[jn * 8]),
                                       __float_as_uint(v0p[VSTR + jn * 8]) };
                    mma_tf32(oacc[jn], ap, bv);
                }
            }
        }
    }

    // epilogue: normalize, write half (feeds proj GEMM)
    float inv0 = 1.f / lrow0;
    float inv1 = 1.f / lrow1;
    __half* ob0 = o + ((size_t)(b * T_ + r0)) * C_ + h * HS_;
    __half* ob1 = ob0 + (size_t)8 * C_;
    #pragma unroll
    for (int j = 0; j < 8; j++) {
        int col = j * 8 + 2 * tg;
        *(__half2*)(ob0 + col) = __floats2half2_rn(oacc[j][0] * inv0, oacc[j][1] * inv0);
        *(__half2*)(ob1 + col) = __floats2half2_rn(oacc[j][2] * inv1, oacc[j][3] * inv1);
    }
}

// ---------------- launch ----------------
extern "C" void kernel_launch(void* const* d_in, const int* in_sizes, int n_in,
                              void* d_out, int out_size)
{
    const float* x     = (const float*)d_in[0];
    const float* Wq    = (const float*)d_in[1];
    const float* Wk    = (const float*)d_in[2];
    const float* Wv    = (const float*)d_in[3];
    const float* Wproj = (const float*)d_in[4];
    const float* bproj = (const float*)d_in[5];
    const float* W1    = (const float*)d_in[6];
    const float* b1    = (const float*)d_in[7];
    const float* W2    = (const float*)d_in[8];
    const float* b2    = (const float*)d_in[9];
    const float* ln1g  = (const float*)d_in[10];
    const float* ln1b  = (const float*)d_in[11];
    const float* ln2g  = (const float*)d_in[12];
    const float* ln2b  = (const float*)d_in[13];
    float* out = (float*)d_out;

    __half *h, *ob, *ff, *wqkv, *wp, *w1, *w2;
    float *qkv, *x1;
    cudaGetSymbolAddress((void**)&h,    g_h);
    cudaGetSymbolAddress((void**)&qkv,  g_qkv);
    cudaGetSymbolAddress((void**)&ob,   g_o);
    cudaGetSymbolAddress((void**)&x1,   g_x1);
    cudaGetSymbolAddress((void**)&ff,   g_ff);
    cudaGetSymbolAddress((void**)&wqkv, g_wqkv);
    cudaGetSymbolAddress((void**)&wp,   g_wp);
    cudaGetSymbolAddress((void**)&w1,   g_w1);
    cudaGetSymbolAddress((void**)&w2,   g_w2);

    cudaFuncSetAttribute(gemm_fp16, cudaFuncAttributeMaxDynamicSharedMemorySize, HG_SMEM);
    cudaFuncSetAttribute(attn_tc,   cudaFuncAttributeMaxDynamicSharedMemorySize, ATTN_SMEM);

    dim3 tb(32, 8);

    // 1. LN1 -> half
    ln_kernel<<<M_, 256>>>(x, ln1g, ln1b, h);

    // 2. qkv weight repack (needed by launch 4)
    repack_qkv3T<<<(C3_*C_)/256, 256>>>(Wq, Wk, Wv, wqkv);

    // 3. Wproj transpose (needed by launch 6)
    transpose_h<<<dim3(C_/32,  C_/32),  tb>>>(Wproj, wp, C_,  C_);

    // 4. fused QKV projection -> fp32 (tf32-rounded)   [ncu profile slot]
    gemm_fp16<<<dim3(M_/256, C3_/128), 256, HG_SMEM>>>(h, wqkv, qkv, M_, C3_, C_,
                                                       nullptr, nullptr, 0, 1);

    // 5. tf32 causal flash attention -> half g_o
    dim3 ga(T_/128, H_, B_);
    attn_tc<<<ga, 256, ATTN_SMEM>>>(qkv, ob);

    // 6. x1 = x + o @ Wproj + bproj  (fp32 out)
    gemm_fp16<<<dim3(M_/256, C_/128), 256, HG_SMEM>>>(ob, wp, x1, M_, C_, C_,
                                                      bproj, x, 0, 0);

    // 7. LN2 -> half
    ln_kernel<<<M_, 256>>>(x1, ln2g, ln2b, h);

    // 8. W1 transpose
    transpose_h<<<dim3(FF_/32, C_/32),  tb>>>(W1, w1, C_, FF_);

    // 9. ff = relu(h @ W1 + b1) -> half
    gemm_fp16<<<dim3(M_/256, FF_/128), 256, HG_SMEM>>>(h, w1, ff, M_, FF_, C_,
                                                       b1, nullptr, 1, 2);

    // 10. W2 transpose
    transpose_h<<<dim3(C_/32,  FF_/32), tb>>>(W2, w2, FF_, C_);

    // 11. out = x1 + ff @ W2 + b2  (final, fp32 out)
    gemm_fp16<<<dim3(M_/256, C_/128), 256, HG_SMEM>>>(ff, w2, out, M_, C_, FF_,
                                                      b2, x1, 0, 0);
}

// round 9
// speedup vs baseline: 1.1250x; 1.1250x over previous
#include <cuda_runtime.h>
#include <cuda_fp16.h>
#include <math.h>
#include <stdint.h>

// Problem constants
#define B_  4
#define T_  2048
#define C_  1024
#define C3_ 3072
#define H_  16
#define HS_ 64
#define FF_ 4096
#define M_  (B_*T_)     // 8192 rows
#define EPS_ 1e-5f

// ---------------- scratch (no dynamic alloc allowed) ----------------
__device__ __half g_h   [M_*C_];    // LN output (half)
__device__ float  g_qkv [M_*C3_];   // fused q|k|v fp32 (tf32-rounded) for attention
__device__ __half g_o   [M_*C_];    // attention output (half)
__device__ float  g_x1  [M_*C_];    // x + attn_out @ Wproj + bproj (fp32)
__device__ __half g_ff  [M_*FF_];   // relu(h2 @ W1 + b1) (half)
__device__ __half g_wqkv[C3_*C_];   // repacked+transposed [3C, C] qkv weight (half)
__device__ __half g_wp  [C_*C_];    // transposed Wproj [N,K] (half)
__device__ __half g_w1  [FF_*C_];   // transposed W1 [4096,1024] (half)
__device__ __half g_w2  [C_*FF_];   // transposed W2 [1024,4096] (half)

__device__ __forceinline__ uint32_t f2tf32(float f) {
    uint32_t u;
    asm("cvt.rna.tf32.f32 %0, %1;" : "=r"(u) : "f"(f));
    return u;
}
__device__ __forceinline__ float roundtf(float f) {
    return __uint_as_float(f2tf32(f));
}

// tf32 mma (attention)
__device__ __forceinline__ void mma_tf32(float* c, const uint32_t* a, const uint32_t* b) {
    asm volatile("mma.sync.aligned.m16n8k8.row.col.f32.tf32.tf32.f32 "
        "{%0,%1,%2,%3}, {%4,%5,%6,%7}, {%8,%9}, {%0,%1,%2,%3};"
        : "+f"(c[0]), "+f"(c[1]), "+f"(c[2]), "+f"(c[3])
        : "r"(a[0]), "r"(a[1]), "r"(a[2]), "r"(a[3]), "r"(b[0]), "r"(b[1]));
}
// fp16 mma (GEMMs)
__device__ __forceinline__ void mma_fp16(float* c, const uint32_t* a, const uint32_t* b) {
    asm volatile("mma.sync.aligned.m16n8k16.row.col.f32.f16.f16.f32 "
        "{%0,%1,%2,%3}, {%4,%5,%6,%7}, {%8,%9}, {%0,%1,%2,%3};"
        : "+f"(c[0]), "+f"(c[1]), "+f"(c[2]), "+f"(c[3])
        : "r"(a[0]), "r"(a[1]), "r"(a[2]), "r"(a[3]), "r"(b[0]), "r"(b[1]));
}
__device__ __forceinline__ void ldm_x4(uint32_t* r, uint32_t addr) {
    asm volatile("ldmatrix.sync.aligned.m8n8.x4.shared.b16 {%0,%1,%2,%3}, [%4];"
        : "=r"(r[0]), "=r"(r[1]), "=r"(r[2]), "=r"(r[3]) : "r"(addr));
}
__device__ __forceinline__ uint32_t smem_u32(const void* p) {
    return (uint32_t)__cvta_generic_to_shared(p);
}

// ---------------- LayerNorm: fp32 in, half out ----------------
__global__ __launch_bounds__(256) void ln_kernel(const float* __restrict__ x,
                                                 const float* __restrict__ g,
                                                 const float* __restrict__ b,
                                                 __half* __restrict__ y)
{
    int row = blockIdx.x;
    const float* xr = x + (size_t)row * C_;
    __half* yr = y + (size_t)row * C_;
    int tid = threadIdx.x;

    float s = 0.f, s2 = 0.f;
    #pragma unroll
    for (int i = tid; i < C_; i += 256) {
        float v = xr[i];
        s += v; s2 += v * v;
    }
    __shared__ float rs[256], rs2[256];
    rs[tid] = s; rs2[tid] = s2;
    __syncthreads();
    for (int off = 128; off > 0; off >>= 1) {
        if (tid < off) { rs[tid] += rs[tid+off]; rs2[tid] += rs2[tid+off]; }
        __syncthreads();
    }
    float mean = rs[0] * (1.0f / C_);
    float var  = rs2[0] * (1.0f / C_) - mean * mean;
    float rstd = rsqrtf(var + EPS_);
    #pragma unroll
    for (int i = tid; i < C_; i += 256) {
        yr[i] = __float2half_rn((xr[i] - mean) * rstd * g[i] + b[i]);
    }
}

// ---------------- repack [H,C,HS]x3 -> [3C, C] half ----------------
__global__ void repack_qkv3T(const float* __restrict__ Wq,
                             const float* __restrict__ Wk,
                             const float* __restrict__ Wv,
                             __half* __restrict__ Wt)
{
    int idx = blockIdx.x * 256 + threadIdx.x;   // idx = n*C + c
    if (idx < C3_*C_) {
        int n = idx >> 10;
        int c = idx & (C_ - 1);
        int sec = n >> 10;
        int nn = n & (C_ - 1);
        int h = nn >> 6;
        int d = nn & (HS_ - 1);
        const float* W = (sec == 0) ? Wq : (sec == 1) ? Wk : Wv;
        Wt[idx] = __float2half_rn(W[(size_t)h * C_ * HS_ + (size_t)c * HS_ + d]);
    }
}

// ---------------- transpose to half: src [R, Cc] fp32 -> dst [Cc, R] half -------
__global__ void transpose_h(const float* __restrict__ S, __half* __restrict__ D,
                            int R, int Cc)
{
    __shared__ float t[32][33];
    int bx = blockIdx.x * 32, by = blockIdx.y * 32;
    int x = threadIdx.x, y = threadIdx.y;
    #pragma unroll
    for (int i = 0; i < 32; i += 8)
        t[y + i][x] = S[(size_t)(by + y + i) * Cc + bx + x];
    __syncthreads();
    #pragma unroll
    for (int i = 0; i < 32; i += 8)
        D[(size_t)(bx + y + i) * R + by + x] = __float2half_rn(t[x][y + i]);
}

// ---------------- fp16 mma.sync GEMM with ldmatrix fragments ----------------
// C[M,N] = A[M,K] @ Bt[N,K]^T  (+bias)(+res)(relu)
// out_mode: 0 = fp32, 1 = fp32 tf32-rounded, 2 = half
// 128x128 CTA tile, BK=32 halves, 8 warps at 64x32, 4-stage cp.async, 2 CTA/SM.
// HSTR=40 halves (80B rows): every ldmatrix 8-lane phase hits word-banks
// 20r mod 32 = full permutation -> conflict-free.
#define HSTR 40
#define HG_STAGE (2*128*HSTR)          // halves per stage (A+B) = 10240
#define HG_SMEM  (4*HG_STAGE*2)        // 81920 bytes

__global__ __launch_bounds__(256, 2) void gemm_fp16(const __half* __restrict__ A,
                                                    const __half* __restrict__ Bt,
                                                    void* __restrict__ Cm,
                                                    int Mn, int Nn, int Kn,
                                                    const float* __restrict__ bias,
                                                    const float* __restrict__ res,
                                                    int relu, int out_mode)
{
    extern __shared__ __half smh[];
    const int tid = threadIdx.x;
    const int wid = tid >> 5, lane = tid & 31;
    const int g = lane >> 2, tg = lane & 3;
    const int warp_m = wid >> 2;       // 0..1  (64 rows)
    const int warp_n = wid & 3;        // 0..3  (32 cols)
    const int bm = blockIdx.x * 128;
    const int bn = blockIdx.y * 128;

    // ldmatrix lane address components
    const int a_row  = lane & 15;                         // row within 16-row A tile
    const int a_koff = (lane >> 4) << 3;                  // 0 or 8 halves
    const int b_row  = ((lane >> 4) << 3) + (lane & 7);   // n within 16-n B pair
    const int b_koff = ((lane >> 3) & 1) << 3;            // 0 or 8 halves

    float acc[4][4][4];
    #pragma unroll
    for (int mi = 0; mi < 4; mi++)
        #pragma unroll
        for (int ni = 0; ni < 4; ni++)
            #pragma unroll
            for (int r = 0; r < 4; r++) acc[mi][ni][r] = 0.f;

    auto fill = [&](int s, int kt) {
        const int k0 = kt << 5;
        __half* As = smh + s * HG_STAGE;
        __half* Bs = As + 128 * HSTR;
        #pragma unroll
        for (int i = 0; i < 2; i++) {
            int idx = tid + (i << 8);          // 512 chunks of 16B (8 halves) each
            int r = idx >> 2, c8 = (idx & 3) << 3;
            uint32_t da = smem_u32(As + r * HSTR + c8);
            asm volatile("cp.async.cg.shared.global [%0], [%1], 16;"
                         :: "r"(da), "l"(A + (size_t)(bm + r) * Kn + k0 + c8));
            uint32_t db = smem_u32(Bs + r * HSTR + c8);
            asm volatile("cp.async.cg.shared.global [%0], [%1], 16;"
                         :: "r"(db), "l"(Bt + (size_t)(bn + r) * Kn + k0 + c8));
        }
        asm volatile("cp.async.commit_group;");
    };

    const int KT = Kn >> 5;
    fill(0, 0);
    fill(1, 1);
    fill(2, 2);

    for (int kt = 0; kt < KT; kt++) {
        if (kt + 2 < KT)      asm volatile("cp.async.wait_group 2;");
        else if (kt + 1 < KT) asm volatile("cp.async.wait_group 1;");
        else                  asm volatile("cp.async.wait_group 0;");
        __syncthreads();
        if (kt + 3 < KT) fill((kt + 3) & 3, kt + 3);

        const __half* As = smh + (kt & 3) * HG_STAGE;
        const __half* Bs = As + 128 * HSTR;

        #pragma unroll
        for (int ks = 0; ks < 2; ks++) {
            const int kb0 = ks * 16;
            uint32_t af[4][4], bq[2][4];
            #pragma unroll
            for (int mi = 0; mi < 4; mi++)
                ldm_x4(af[mi], smem_u32(As + (warp_m * 64 + mi * 16 + a_row) * HSTR
                                           + kb0 + a_koff));
            #pragma unroll
            for (int np = 0; np < 2; np++)
                ldm_x4(bq[np], smem_u32(Bs + (warp_n * 32 + np * 16 + b_row) * HSTR
                                           + kb0 + b_koff));
            #pragma unroll
            for (int mi = 0; mi < 4; mi++)
                #pragma unroll
                for (int ni = 0; ni < 4; ni++)
                    mma_fp16(acc[mi][ni], af[mi], &bq[ni >> 1][(ni & 1) * 2]);
        }
    }

    // epilogue: c0/c1 = row g cols 2tg,2tg+1; c2/c3 at row g+8
    #pragma unroll
    for (int mi = 0; mi < 4; mi++) {
        #pragma unroll
        for (int ni = 0; ni < 4; ni++) {
            int row0 = bm + warp_m * 64 + mi * 16 + g;
            int col  = bn + warp_n * 32 + ni * 8 + tg * 2;
            float bx = 0.f, by = 0.f;
            if (bias) { bx = bias[col]; by = bias[col + 1]; }
            #pragma unroll
            for (int half_ = 0; half_ < 2; half_++) {
                int row = row0 + half_ * 8;
                float v0 = acc[mi][ni][half_ * 2 + 0] + bx;
                float v1 = acc[mi][ni][half_ * 2 + 1] + by;
                if (res) {
                    const float* rp = res + (size_t)row * Nn + col;
                    v0 += rp[0]; v1 += rp[1];
                }
                if (relu) { v0 = fmaxf(v0, 0.f); v1 = fmaxf(v1, 0.f); }
                if (out_mode == 2) {
                    __half2 hv = __floats2half2_rn(v0, v1);
                    *(__half2*)((__half*)Cm + (size_t)row * Nn + col) = hv;
                } else {
                    if (out_mode == 1) { v0 = roundtf(v0); v1 = roundtf(v1); }
                    *(float2*)((float*)Cm + (size_t)row * Nn + col) = make_float2(v0, v1);
                }
            }
        }
    }
}

// ---------------- tensor-core flash attention (tf32, register-resident P) -------
// fp32 qkv in, half out. 128 queries/block, 8 warps, 64-key tiles.
#define KSTR 68
#define VSTR 68
#define PSTR 68
#define ATTN_SMEM ((2*64*KSTR + 2*64*VSTR + 128*PSTR)*4)   // 104448

__global__ __launch_bounds__(256, 2) void attn_tc(const float* __restrict__ qkv,
                                                  __half* __restrict__ o)
{
    extern __shared__ float sm[];
    float* Ks = sm;                      // 2 stages of 64 x KSTR
    float* Vs = sm + 2*64*KSTR;          // 2 stages of 64 x VSTR
    float* Ps = Vs + 2*64*VSTR;          // 128 x PSTR (Q staging, pre-scaled)

    const int tid = threadIdx.x, wid = tid >> 5, lane = tid & 31;
    const int g = lane >> 2, tg = lane & 3;
    const int qt0 = blockIdx.x * 128;
    const int h = blockIdx.y, b = blockIdx.z;

    const float* qbase = qkv + (size_t)(b * T_ + qt0) * C3_ + h * HS_;
    const float* kbase = qkv + (size_t)b * T_ * C3_ + C_  + h * HS_;
    const float* vbase = qkv + (size_t)b * T_ * C3_ + 2*C_ + h * HS_;

    // stage Q tile (128x64), pre-scaled by 1/8 (exact in tf32)
    {
        int r = tid >> 1, c = (tid & 1) * 32;
        #pragma unroll
        for (int cc = 0; cc < 8; cc++) {
            float4 v = *(const float4*)(qbase + (size_t)r * C3_ + c + cc * 4);
            v.x *= 0.125f; v.y *= 0.125f; v.z *= 0.125f; v.w *= 0.125f;
            *(float4*)&Ps[r * PSTR + c + cc * 4] = v;
        }
    }

    float mrow0 = -INFINITY, mrow1 = -INFINITY, lrow0 = 0.f, lrow1 = 0.f;
    float oacc[8][4];
    #pragma unroll
    for (int j = 0; j < 8; j++)
        #pragma unroll
        for (int r = 0; r < 4; r++) oacc[j][r] = 0.f;

    const int m0 = wid * 16;
    const int r0 = qt0 + m0 + g;
    const int my_max = qt0 + m0 + 15;
    const int ntiles = (qt0 + 128) >> 6;

    auto loadKV = [&](int s, int s0) {
        const float* kp = kbase + (size_t)s0 * C3_;
        const float* vp = vbase + (size_t)s0 * C3_;
        float* Kd = Ks + s * 64 * KSTR;
        float* Vd = Vs + s * 64 * VSTR;
        #pragma unroll
        for (int i = 0; i < 4; i++) {
            int idx = tid + i * 256;
            int r = idx >> 4, c = (idx & 15) * 4;
            uint32_t dk = smem_u32(Kd + r * KSTR + c);
            asm volatile("cp.async.cg.shared.global [%0], [%1], 16;"
                         :: "r"(dk), "l"(kp + (size_t)r * C3_ + c));
            uint32_t dv = smem_u32(Vd + r * VSTR + c);
            asm volatile("cp.async.cg.shared.global [%0], [%1], 16;"
                         :: "r"(dv), "l"(vp + (size_t)r * C3_ + c));
        }
        asm volatile("cp.async.commit_group;");
    };

    loadKV(0, 0);
    __syncthreads();   // Q staging visible (and ordered before first compute)

    for (int t = 0; t < ntiles; t++) {
        const int s0 = t * 64;
        asm volatile("cp.async.wait_group 0;");
        __syncthreads();
        if (t + 1 < ntiles) loadKV((t + 1) & 1, s0 + 64);

        if (s0 <= my_max) {
            const float* Kt = Ks + (t & 1) * 64 * KSTR;
            const float* Vt = Vs + (t & 1) * 64 * VSTR;

            // S = (Q/8) @ K^T  (k-lane remap sigma(tg)=2tg)
            float sf[8][4];
            #pragma unroll
            for (int j = 0; j < 8; j++)
                #pragma unroll
                for (int r = 0; r < 4; r++) sf[j][r] = 0.f;
            #pragma unroll
            for (int k = 0; k < 8; k++) {
                const int kb = k * 8 + 2 * tg;
                uint32_t aq[4];
                {
                    float2 lo = *(const float2*)(Ps + (m0 + g) * PSTR + kb);
                    float2 hi = *(const float2*)(Ps + (m0 + g + 8) * PSTR + kb);
                    aq[0] = __float_as_uint(lo.x);
                    aq[1] = __float_as_uint(hi.x);
                    aq[2] = __float_as_uint(lo.y);
                    aq[3] = __float_as_uint(hi.y);
                }
                #pragma unroll
                for (int j = 0; j < 8; j++) {
                    float2 kv = *(const float2*)(Kt + (j * 8 + g) * KSTR + kb);
                    uint32_t bk[2] = { __float_as_uint(kv.x), __float_as_uint(kv.y) };
                    mma_tf32(sf[j], aq, bk);
                }
            }

            // causal mask + online softmax
            float mx0 = -INFINITY, mx1 = -INFINITY;
            #pragma unroll
            for (int j = 0; j < 8; j++) {
                int c0 = s0 + j * 8 + 2 * tg, c1 = c0 + 1;
                if (c0 > r0)     sf[j][0] = -INFINITY;
                if (c1 > r0)     sf[j][1] = -INFINITY;
                if (c0 > r0 + 8) sf[j][2] = -INFINITY;
                if (c1 > r0 + 8) sf[j][3] = -INFINITY;
                mx0 = fmaxf(mx0, fmaxf(sf[j][0], sf[j][1]));
                mx1 = fmaxf(mx1, fmaxf(sf[j][2], sf[j][3]));
            }
            mx0 = fmaxf(mx0, __shfl_xor_sync(0xffffffffu, mx0, 1));
            mx0 = fmaxf(mx0, __shfl_xor_sync(0xffffffffu, mx0, 2));
            mx1 = fmaxf(mx1, __shfl_xor_sync(0xffffffffu, mx1, 1));
            mx1 = fmaxf(mx1, __shfl_xor_sync(0xffffffffu, mx1, 2));

            float mn0 = fmaxf(mrow0, mx0), mn1 = fmaxf(mrow1, mx1);
            float corr0 = __expf(mrow0 - mn0), corr1 = __expf(mrow1 - mn1);
            float sum0 = 0.f, sum1 = 0.f;
            #pragma unroll
            for (int j = 0; j < 8; j++) {
                sf[j][0] = __expf(sf[j][0] - mn0);
                sf[j][1] = __expf(sf[j][1] - mn0);
                sf[j][2] = __expf(sf[j][2] - mn1);
                sf[j][3] = __expf(sf[j][3] - mn1);
                sum0 += sf[j][0] + sf[j][1];
                sum1 += sf[j][2] + sf[j][3];
            }
            sum0 += __shfl_xor_sync(0xffffffffu, sum0, 1);
            sum0 += __shfl_xor_sync(0xffffffffu, sum0, 2);
            sum1 += __shfl_xor_sync(0xffffffffu, sum1, 1);
            sum1 += __shfl_xor_sync(0xffffffffu, sum1, 2);
            lrow0 = lrow0 * corr0 + sum0;
            lrow1 = lrow1 * corr1 + sum1;
            mrow0 = mn0; mrow1 = mn1;
            #pragma unroll
            for (int j = 0; j < 8; j++) {
                oacc[j][0] *= corr0; oacc[j][1] *= corr0;
                oacc[j][2] *= corr1; oacc[j][3] *= corr1;
            }

            // O += P @ V : A-frag = score C-frag (in-register, tf32-rounded)
            #pragma unroll
            for (int kk = 0; kk < 8; kk++) {
                uint32_t ap[4] = { f2tf32(sf[kk][0]), f2tf32(sf[kk][2]),
                                   f2tf32(sf[kk][1]), f2tf32(sf[kk][3]) };
                const float* v0p = Vt + (kk * 8 + 2 * tg) * VSTR + g;
                #pragma unroll
                for (int jn = 0; jn < 8; jn++) {
                    uint32_t bv[2] = { __float_as_uint(v0p[jn * 8]),
                                       __float_as_uint(v0p[VSTR + jn * 8]) };
                    mma_tf32(oacc[jn], ap, bv);
                }
            }
        }
    }

    // epilogue: normalize, write half (feeds proj GEMM)
    float inv0 = 1.f / lrow0;
    float inv1 = 1.f / lrow1;
    __half* ob0 = o + ((size_t)(b * T_ + r0)) * C_ + h * HS_;
    __half* ob1 = ob0 + (size_t)8 * C_;
    #pragma unroll
    for (int j = 0; j < 8; j++) {
        int col = j * 8 + 2 * tg;
        *(__half2*)(ob0 + col) = __floats2half2_rn(oacc[j][0] * inv0, oacc[j][1] * inv0);
        *(__half2*)(ob1 + col) = __floats2half2_rn(oacc[j][2] * inv1, oacc[j][3] * inv1);
    }
}

// ---------------- launch ----------------
extern "C" void kernel_launch(void* const* d_in, const int* in_sizes, int n_in,
                              void* d_out, int out_size)
{
    const float* x     = (const float*)d_in[0];
    const float* Wq    = (const float*)d_in[1];
    const float* Wk    = (const float*)d_in[2];
    const float* Wv    = (const float*)d_in[3];
    const float* Wproj = (const float*)d_in[4];
    const float* bproj = (const float*)d_in[5];
    const float* W1    = (const float*)d_in[6];
    const float* b1    = (const float*)d_in[7];
    const float* W2    = (const float*)d_in[8];
    const float* b2    = (const float*)d_in[9];
    const float* ln1g  = (const float*)d_in[10];
    const float* ln1b  = (const float*)d_in[11];
    const float* ln2g  = (const float*)d_in[12];
    const float* ln2b  = (const float*)d_in[13];
    float* out = (float*)d_out;

    __half *h, *ob, *ff, *wqkv, *wp, *w1, *w2;
    float *qkv, *x1;
    cudaGetSymbolAddress((void**)&h,    g_h);
    cudaGetSymbolAddress((void**)&qkv,  g_qkv);
    cudaGetSymbolAddress((void**)&ob,   g_o);
    cudaGetSymbolAddress((void**)&x1,   g_x1);
    cudaGetSymbolAddress((void**)&ff,   g_ff);
    cudaGetSymbolAddress((void**)&wqkv, g_wqkv);
    cudaGetSymbolAddress((void**)&wp,   g_wp);
    cudaGetSymbolAddress((void**)&w1,   g_w1);
    cudaGetSymbolAddress((void**)&w2,   g_w2);

    cudaFuncSetAttribute(gemm_fp16, cudaFuncAttributeMaxDynamicSharedMemorySize, HG_SMEM);
    cudaFuncSetAttribute(attn_tc,   cudaFuncAttributeMaxDynamicSharedMemorySize, ATTN_SMEM);

    dim3 tb(32, 8);

    // 1. LN1 -> half
    ln_kernel<<<M_, 256>>>(x, ln1g, ln1b, h);

    // 2. qkv weight repack (needed by launch 4)
    repack_qkv3T<<<(C3_*C_)/256, 256>>>(Wq, Wk, Wv, wqkv);

    // 3. Wproj transpose (needed by launch 6)
    transpose_h<<<dim3(C_/32,  C_/32),  tb>>>(Wproj, wp, C_,  C_);

    // 4. fused QKV projection -> fp32 (tf32-rounded)   [ncu profile slot]
    gemm_fp16<<<dim3(M_/128, C3_/128), 256, HG_SMEM>>>(h, wqkv, qkv, M_, C3_, C_,
                                                       nullptr, nullptr, 0, 1);

    // 5. tf32 causal flash attention -> half g_o
    dim3 ga(T_/128, H_, B_);
    attn_tc<<<ga, 256, ATTN_SMEM>>>(qkv, ob);

    // 6. x1 = x + o @ Wproj + bproj  (fp32 out)
    gemm_fp16<<<dim3(M_/128, C_/128), 256, HG_SMEM>>>(ob, wp, x1, M_, C_, C_,
                                                      bproj, x, 0, 0);

    // 7. LN2 -> half
    ln_kernel<<<M_, 256>>>(x1, ln2g, ln2b, h);

    // 8. W1 transpose
    transpose_h<<<dim3(FF_/32, C_/32),  tb>>>(W1, w1, C_, FF_);

    // 9. ff = relu(h @ W1 + b1) -> half
    gemm_fp16<<<dim3(M_/128, FF_/128), 256, HG_SMEM>>>(h, w1, ff, M_, FF_, C_,
                                                       b1, nullptr, 1, 2);

    // 10. W2 transpose
    transpose_h<<<dim3(C_/32,  FF_/32), tb>>>(W2, w2, FF_, C_);

    // 11. out = x1 + ff @ W2 + b2  (final, fp32 out)
    gemm_fp16<<<dim3(M_/128, C_/128), 256, HG_SMEM>>>(ff, w2, out, M_, C_, FF_,
                                                      b2, x1, 0, 0);
}

// round 10
// speedup vs baseline: 1.3657x; 1.2140x over previous
#include <cuda_runtime.h>
#include <cuda_fp16.h>
#include <math.h>
#include <stdint.h>

// Problem constants
#define B_  4
#define T_  2048
#define C_  1024
#define C3_ 3072
#define H_  16
#define HS_ 64
#define FF_ 4096
#define M_  (B_*T_)     // 8192 rows
#define EPS_ 1e-5f

// ---------------- scratch (no dynamic alloc allowed) ----------------
__device__ __half g_h   [M_*C_];    // LN output (half)
__device__ __half g_qkv [M_*C3_];   // fused q|k|v (half), row stride 3072
__device__ __half g_o   [M_*C_];    // attention output (half)
__device__ float  g_x1  [M_*C_];    // x + attn_out @ Wproj + bproj (fp32)
__device__ __half g_ff  [M_*FF_];   // relu(h2 @ W1 + b1) (half)
__device__ __half g_wqkv[C3_*C_];   // repacked+transposed [3C, C] qkv weight (half)
__device__ __half g_wp  [C_*C_];    // transposed Wproj [N,K] (half)
__device__ __half g_w1  [FF_*C_];   // transposed W1 [4096,1024] (half)
__device__ __half g_w2  [C_*FF_];   // transposed W2 [1024,4096] (half)

__device__ __forceinline__ uint32_t f2tf32(float f) {
    uint32_t u;
    asm("cvt.rna.tf32.f32 %0, %1;" : "=r"(u) : "f"(f));
    return u;
}
__device__ __forceinline__ float roundtf(float f) {
    return __uint_as_float(f2tf32(f));
}

// fp16 mma (GEMMs + attention)
__device__ __forceinline__ void mma_fp16(float* c, const uint32_t* a, const uint32_t* b) {
    asm volatile("mma.sync.aligned.m16n8k16.row.col.f32.f16.f16.f32 "
        "{%0,%1,%2,%3}, {%4,%5,%6,%7}, {%8,%9}, {%0,%1,%2,%3};"
        : "+f"(c[0]), "+f"(c[1]), "+f"(c[2]), "+f"(c[3])
        : "r"(a[0]), "r"(a[1]), "r"(a[2]), "r"(a[3]), "r"(b[0]), "r"(b[1]));
}
__device__ __forceinline__ void mma_fp16_2(float* c, const uint32_t* a,
                                           uint32_t b0, uint32_t b1) {
    asm volatile("mma.sync.aligned.m16n8k16.row.col.f32.f16.f16.f32 "
        "{%0,%1,%2,%3}, {%4,%5,%6,%7}, {%8,%9}, {%0,%1,%2,%3};"
        : "+f"(c[0]), "+f"(c[1]), "+f"(c[2]), "+f"(c[3])
        : "r"(a[0]), "r"(a[1]), "r"(a[2]), "r"(a[3]), "r"(b0), "r"(b1));
}
__device__ __forceinline__ void ldm_x4(uint32_t* r, uint32_t addr) {
    asm volatile("ldmatrix.sync.aligned.m8n8.x4.shared.b16 {%0,%1,%2,%3}, [%4];"
        : "=r"(r[0]), "=r"(r[1]), "=r"(r[2]), "=r"(r[3]) : "r"(addr));
}
__device__ __forceinline__ void ldm_x4_t(uint32_t* r, uint32_t addr) {
    asm volatile("ldmatrix.sync.aligned.m8n8.x4.trans.shared.b16 {%0,%1,%2,%3}, [%4];"
        : "=r"(r[0]), "=r"(r[1]), "=r"(r[2]), "=r"(r[3]) : "r"(addr));
}
__device__ __forceinline__ uint32_t pack_h2(float lo, float hi) {
    __half2 h = __floats2half2_rn(lo, hi);
    return *reinterpret_cast<uint32_t*>(&h);
}
__device__ __forceinline__ uint32_t smem_u32(const void* p) {
    return (uint32_t)__cvta_generic_to_shared(p);
}

// ---------------- LayerNorm: fp32 in, half out ----------------
__global__ __launch_bounds__(256) void ln_kernel(const float* __restrict__ x,
                                                 const float* __restrict__ g,
                                                 const float* __restrict__ b,
                                                 __half* __restrict__ y)
{
    int row = blockIdx.x;
    const float* xr = x + (size_t)row * C_;
    __half* yr = y + (size_t)row * C_;
    int tid = threadIdx.x;

    float s = 0.f, s2 = 0.f;
    #pragma unroll
    for (int i = tid; i < C_; i += 256) {
        float v = xr[i];
        s += v; s2 += v * v;
    }
    __shared__ float rs[256], rs2[256];
    rs[tid] = s; rs2[tid] = s2;
    __syncthreads();
    for (int off = 128; off > 0; off >>= 1) {
        if (tid < off) { rs[tid] += rs[tid+off]; rs2[tid] += rs2[tid+off]; }
        __syncthreads();
    }
    float mean = rs[0] * (1.0f / C_);
    float var  = rs2[0] * (1.0f / C_) - mean * mean;
    float rstd = rsqrtf(var + EPS_);
    #pragma unroll
    for (int i = tid; i < C_; i += 256) {
        yr[i] = __float2half_rn((xr[i] - mean) * rstd * g[i] + b[i]);
    }
}

// ---------------- repack [H,C,HS]x3 -> [3C, C] half ----------------
__global__ void repack_qkv3T(const float* __restrict__ Wq,
                             const float* __restrict__ Wk,
                             const float* __restrict__ Wv,
                             __half* __restrict__ Wt)
{
    int idx = blockIdx.x * 256 + threadIdx.x;   // idx = n*C + c
    if (idx < C3_*C_) {
        int n = idx >> 10;
        int c = idx & (C_ - 1);
        int sec = n >> 10;
        int nn = n & (C_ - 1);
        int h = nn >> 6;
        int d = nn & (HS_ - 1);
        const float* W = (sec == 0) ? Wq : (sec == 1) ? Wk : Wv;
        Wt[idx] = __float2half_rn(W[(size_t)h * C_ * HS_ + (size_t)c * HS_ + d]);
    }
}

// ---------------- transpose to half: src [R, Cc] fp32 -> dst [Cc, R] half -------
__global__ void transpose_h(const float* __restrict__ S, __half* __restrict__ D,
                            int R, int Cc)
{
    __shared__ float t[32][33];
    int bx = blockIdx.x * 32, by = blockIdx.y * 32;
    int x = threadIdx.x, y = threadIdx.y;
    #pragma unroll
    for (int i = 0; i < 32; i += 8)
        t[y + i][x] = S[(size_t)(by + y + i) * Cc + bx + x];
    __syncthreads();
    #pragma unroll
    for (int i = 0; i < 32; i += 8)
        D[(size_t)(bx + y + i) * R + by + x] = __float2half_rn(t[x][y + i]);
}

// ---------------- fp16 mma.sync GEMM with ldmatrix fragments ----------------
// C[M,N] = A[M,K] @ Bt[N,K]^T  (+bias)(+res)(relu)
// out_mode: 0 = fp32, 1 = fp32 tf32-rounded, 2 = half
// 128x128 CTA tile, BK=32 halves, 8 warps at 64x32, 4-stage cp.async, 2 CTA/SM.
#define HSTR 40
#define HG_STAGE (2*128*HSTR)          // halves per stage (A+B) = 10240
#define HG_SMEM  (4*HG_STAGE*2)        // 81920 bytes

__global__ __launch_bounds__(256, 2) void gemm_fp16(const __half* __restrict__ A,
                                                    const __half* __restrict__ Bt,
                                                    void* __restrict__ Cm,
                                                    int Mn, int Nn, int Kn,
                                                    const float* __restrict__ bias,
                                                    const float* __restrict__ res,
                                                    int relu, int out_mode)
{
    extern __shared__ __half smh[];
    const int tid = threadIdx.x;
    const int wid = tid >> 5, lane = tid & 31;
    const int g = lane >> 2, tg = lane & 3;
    const int warp_m = wid >> 2;       // 0..1  (64 rows)
    const int warp_n = wid & 3;        // 0..3  (32 cols)
    const int bm = blockIdx.x * 128;
    const int bn = blockIdx.y * 128;

    const int a_row  = lane & 15;
    const int a_koff = (lane >> 4) << 3;
    const int b_row  = ((lane >> 4) << 3) + (lane & 7);
    const int b_koff = ((lane >> 3) & 1) << 3;

    float acc[4][4][4];
    #pragma unroll
    for (int mi = 0; mi < 4; mi++)
        #pragma unroll
        for (int ni = 0; ni < 4; ni++)
            #pragma unroll
            for (int r = 0; r < 4; r++) acc[mi][ni][r] = 0.f;

    auto fill = [&](int s, int kt) {
        const int k0 = kt << 5;
        __half* As = smh + s * HG_STAGE;
        __half* Bs = As + 128 * HSTR;
        #pragma unroll
        for (int i = 0; i < 2; i++) {
            int idx = tid + (i << 8);
            int r = idx >> 2, c8 = (idx & 3) << 3;
            uint32_t da = smem_u32(As + r * HSTR + c8);
            asm volatile("cp.async.cg.shared.global [%0], [%1], 16;"
                         :: "r"(da), "l"(A + (size_t)(bm + r) * Kn + k0 + c8));
            uint32_t db = smem_u32(Bs + r * HSTR + c8);
            asm volatile("cp.async.cg.shared.global [%0], [%1], 16;"
                         :: "r"(db), "l"(Bt + (size_t)(bn + r) * Kn + k0 + c8));
        }
        asm volatile("cp.async.commit_group;");
    };

    const int KT = Kn >> 5;
    fill(0, 0);
    fill(1, 1);
    fill(2, 2);

    for (int kt = 0; kt < KT; kt++) {
        if (kt + 2 < KT)      asm volatile("cp.async.wait_group 2;");
        else if (kt + 1 < KT) asm volatile("cp.async.wait_group 1;");
        else                  asm volatile("cp.async.wait_group 0;");
        __syncthreads();
        if (kt + 3 < KT) fill((kt + 3) & 3, kt + 3);

        const __half* As = smh + (kt & 3) * HG_STAGE;
        const __half* Bs = As + 128 * HSTR;

        #pragma unroll
        for (int ks = 0; ks < 2; ks++) {
            const int kb0 = ks * 16;
            uint32_t af[4][4], bq[2][4];
            #pragma unroll
            for (int mi = 0; mi < 4; mi++)
                ldm_x4(af[mi], smem_u32(As + (warp_m * 64 + mi * 16 + a_row) * HSTR
                                           + kb0 + a_koff));
            #pragma unroll
            for (int np = 0; np < 2; np++)
                ldm_x4(bq[np], smem_u32(Bs + (warp_n * 32 + np * 16 + b_row) * HSTR
                                           + kb0 + b_koff));
            #pragma unroll
            for (int mi = 0; mi < 4; mi++)
                #pragma unroll
                for (int ni = 0; ni < 4; ni++)
                    mma_fp16(acc[mi][ni], af[mi], &bq[ni >> 1][(ni & 1) * 2]);
        }
    }

    #pragma unroll
    for (int mi = 0; mi < 4; mi++) {
        #pragma unroll
        for (int ni = 0; ni < 4; ni++) {
            int row0 = bm + warp_m * 64 + mi * 16 + g;
            int col  = bn + warp_n * 32 + ni * 8 + tg * 2;
            float bx = 0.f, by = 0.f;
            if (bias) { bx = bias[col]; by = bias[col + 1]; }
            #pragma unroll
            for (int half_ = 0; half_ < 2; half_++) {
                int row = row0 + half_ * 8;
                float v0 = acc[mi][ni][half_ * 2 + 0] + bx;
                float v1 = acc[mi][ni][half_ * 2 + 1] + by;
                if (res) {
                    const float* rp = res + (size_t)row * Nn + col;
                    v0 += rp[0]; v1 += rp[1];
                }
                if (relu) { v0 = fmaxf(v0, 0.f); v1 = fmaxf(v1, 0.f); }
                if (out_mode == 2) {
                    __half2 hv = __floats2half2_rn(v0, v1);
                    *(__half2*)((__half*)Cm + (size_t)row * Nn + col) = hv;
                } else {
                    if (out_mode == 1) { v0 = roundtf(v0); v1 = roundtf(v1); }
                    *(float2*)((float*)Cm + (size_t)row * Nn + col) = make_float2(v0, v1);
                }
            }
        }
    }
}

// ---------------- fp16 tensor-core flash attention ----------------
// half qkv in, half out. 128 queries/block, 8 warps (m16), 64-key tiles,
// m16n8k16 for QK^T and PV, ldmatrix frags, register-resident P.
// Stride 72 halves: ldmatrix rows hit banks 4r..4r+3 -> conflict-free.
#define AKSTR 72
#define AQSTR 72
#define ATTN_SMEM ((4*64*AKSTR + 128*AQSTR)*2)   // 55296 bytes

__global__ __launch_bounds__(256, 2) void attn_h(const __half* __restrict__ qkv,
                                                 __half* __restrict__ o)
{
    extern __shared__ __half smha[];
    __half* Ks = smha;                    // 2 stages 64 x AKSTR
    __half* Vs = smha + 2*64*AKSTR;       // 2 stages 64 x AKSTR
    __half* Qs = Vs + 2*64*AKSTR;         // 128 x AQSTR (Q, pre-scaled)

    const int tid = threadIdx.x, wid = tid >> 5, lane = tid & 31;
    const int g = lane >> 2, tg = lane & 3;
    const int qt0 = blockIdx.x * 128;
    const int h = blockIdx.y, b = blockIdx.z;

    const __half* qbase = qkv + (size_t)(b * T_ + qt0) * C3_ + h * HS_;
    const __half* kbase = qkv + (size_t)b * T_ * C3_ + C_  + h * HS_;
    const __half* vbase = qkv + (size_t)b * T_ * C3_ + 2*C_ + h * HS_;

    // stage Q tile (128x64 half), pre-scaled by 1/8 (exact)
    {
        int r = tid >> 1, c = (tid & 1) * 32;
        const __half2 s8 = __float2half2_rn(0.125f);
        #pragma unroll
        for (int i = 0; i < 4; i++) {
            __half2 v[4];
            *(uint4*)v = *(const uint4*)(qbase + (size_t)r * C3_ + c + i * 8);
            #pragma unroll
            for (int j = 0; j < 4; j++) v[j] = __hmul2(v[j], s8);
            *(uint4*)(Qs + r * AQSTR + c + i * 8) = *(uint4*)v;
        }
    }

    const int m0 = wid * 16;
    const int r0 = qt0 + m0 + g;
    const int my_max = qt0 + m0 + 15;
    const int ntiles = (qt0 + 128) >> 6;
    const int lrow = lane & 15;
    const int lcol = (lane >> 4) << 3;

    auto loadKV = [&](int s, int s0) {
        const __half* kp = kbase + (size_t)s0 * C3_;
        const __half* vp = vbase + (size_t)s0 * C3_;
        __half* Kd = Ks + s * 64 * AKSTR;
        __half* Vd = Vs + s * 64 * AKSTR;
        #pragma unroll
        for (int i = 0; i < 2; i++) {
            int idx = tid + (i << 8);           // 512 chunks of 16B per matrix
            int r = idx >> 3, c8 = (idx & 7) * 8;
            uint32_t dk = smem_u32(Kd + r * AKSTR + c8);
            asm volatile("cp.async.cg.shared.global [%0], [%1], 16;"
                         :: "r"(dk), "l"(kp + (size_t)r * C3_ + c8));
            uint32_t dv = smem_u32(Vd + r * AKSTR + c8);
            asm volatile("cp.async.cg.shared.global [%0], [%1], 16;"
                         :: "r"(dv), "l"(vp + (size_t)r * C3_ + c8));
        }
        asm volatile("cp.async.commit_group;");
    };

    loadKV(0, 0);
    __syncthreads();      // Q staging visible

    // Q fragments (held in registers for the whole kernel)
    uint32_t qf[4][4];
    #pragma unroll
    for (int kc = 0; kc < 4; kc++)
        ldm_x4(qf[kc], smem_u32(Qs + (m0 + lrow) * AQSTR + kc * 16 + lcol));

    float mrow0 = -INFINITY, mrow1 = -INFINITY, lrow0s = 0.f, lrow1s = 0.f;
    float oacc[8][4];
    #pragma unroll
    for (int j = 0; j < 8; j++)
        #pragma unroll
        for (int r = 0; r < 4; r++) oacc[j][r] = 0.f;

    for (int t = 0; t < ntiles; t++) {
        const int s0 = t * 64;
        asm volatile("cp.async.wait_group 0;");
        __syncthreads();
        if (t + 1 < ntiles) loadKV((t + 1) & 1, s0 + 64);

        if (s0 <= my_max) {
            const __half* Kt = Ks + (t & 1) * 64 * AKSTR;
            const __half* Vt = Vs + (t & 1) * 64 * AKSTR;

            // S = (Q/8) @ K^T : 4 dim-chunks x 8 n-tiles
            float sf[8][4];
            #pragma unroll
            for (int j = 0; j < 8; j++)
                #pragma unroll
                for (int r = 0; r < 4; r++) sf[j][r] = 0.f;
            #pragma unroll
            for (int kc = 0; kc < 4; kc++) {
                #pragma unroll
                for (int jb = 0; jb < 4; jb++) {
                    uint32_t kf[4];
                    ldm_x4(kf, smem_u32(Kt + (jb * 16 + lrow) * AKSTR + kc * 16 + lcol));
                    mma_fp16_2(sf[2*jb],   qf[kc], kf[0], kf[2]);
                    mma_fp16_2(sf[2*jb+1], qf[kc], kf[1], kf[3]);
                }
            }

            // causal mask + online softmax (rows r0, r0+8; cols 2tg,2tg+1)
            float mx0 = -INFINITY, mx1 = -INFINITY;
            #pragma unroll
            for (int j = 0; j < 8; j++) {
                int c0 = s0 + j * 8 + 2 * tg, c1 = c0 + 1;
                if (c0 > r0)     sf[j][0] = -INFINITY;
                if (c1 > r0)     sf[j][1] = -INFINITY;
                if (c0 > r0 + 8) sf[j][2] = -INFINITY;
                if (c1 > r0 + 8) sf[j][3] = -INFINITY;
                mx0 = fmaxf(mx0, fmaxf(sf[j][0], sf[j][1]));
                mx1 = fmaxf(mx1, fmaxf(sf[j][2], sf[j][3]));
            }
            mx0 = fmaxf(mx0, __shfl_xor_sync(0xffffffffu, mx0, 1));
            mx0 = fmaxf(mx0, __shfl_xor_sync(0xffffffffu, mx0, 2));
            mx1 = fmaxf(mx1, __shfl_xor_sync(0xffffffffu, mx1, 1));
            mx1 = fmaxf(mx1, __shfl_xor_sync(0xffffffffu, mx1, 2));

            float mn0 = fmaxf(mrow0, mx0), mn1 = fmaxf(mrow1, mx1);
            float corr0 = __expf(mrow0 - mn0), corr1 = __expf(mrow1 - mn1);
            float sum0 = 0.f, sum1 = 0.f;
            #pragma unroll
            for (int j = 0; j < 8; j++) {
                sf[j][0] = __expf(sf[j][0] - mn0);
                sf[j][1] = __expf(sf[j][1] - mn0);
                sf[j][2] = __expf(sf[j][2] - mn1);
                sf[j][3] = __expf(sf[j][3] - mn1);
                sum0 += sf[j][0] + sf[j][1];
                sum1 += sf[j][2] + sf[j][3];
            }
            sum0 += __shfl_xor_sync(0xffffffffu, sum0, 1);
            sum0 += __shfl_xor_sync(0xffffffffu, sum0, 2);
            sum1 += __shfl_xor_sync(0xffffffffu, sum1, 1);
            sum1 += __shfl_xor_sync(0xffffffffu, sum1, 2);
            lrow0s = lrow0s * corr0 + sum0;
            lrow1s = lrow1s * corr1 + sum1;
            mrow0 = mn0; mrow1 = mn1;
            #pragma unroll
            for (int j = 0; j < 8; j++) {
                oacc[j][0] *= corr0; oacc[j][1] *= corr0;
                oacc[j][2] *= corr1; oacc[j][3] *= corr1;
            }

            // O += P @ V : P A-frags packed in-register; V via ldmatrix.trans
            #pragma unroll
            for (int kk = 0; kk < 4; kk++) {
                uint32_t ap[4];
                ap[0] = pack_h2(sf[2*kk][0],   sf[2*kk][1]);
                ap[1] = pack_h2(sf[2*kk][2],   sf[2*kk][3]);
                ap[2] = pack_h2(sf[2*kk+1][0], sf[2*kk+1][1]);
                ap[3] = pack_h2(sf[2*kk+1][2], sf[2*kk+1][3]);
                #pragma unroll
                for (int db = 0; db < 4; db++) {
                    uint32_t vf[4];
                    ldm_x4_t(vf, smem_u32(Vt + (kk * 16 + lrow) * AKSTR + db * 16 + lcol));
                    mma_fp16_2(oacc[2*db],   ap, vf[0], vf[1]);
                    mma_fp16_2(oacc[2*db+1], ap, vf[2], vf[3]);
                }
            }
        }
    }

    // epilogue: normalize, write half (feeds proj GEMM)
    float inv0 = 1.f / lrow0s;
    float inv1 = 1.f / lrow1s;
    __half* ob0 = o + ((size_t)(b * T_ + r0)) * C_ + h * HS_;
    __half* ob1 = ob0 + (size_t)8 * C_;
    #pragma unroll
    for (int j = 0; j < 8; j++) {
        int col = j * 8 + 2 * tg;
        *(__half2*)(ob0 + col) = __floats2half2_rn(oacc[j][0] * inv0, oacc[j][1] * inv0);
        *(__half2*)(ob1 + col) = __floats2half2_rn(oacc[j][2] * inv1, oacc[j][3] * inv1);
    }
}

// ---------------- launch ----------------
extern "C" void kernel_launch(void* const* d_in, const int* in_sizes, int n_in,
                              void* d_out, int out_size)
{
    const float* x     = (const float*)d_in[0];
    const float* Wq    = (const float*)d_in[1];
    const float* Wk    = (const float*)d_in[2];
    const float* Wv    = (const float*)d_in[3];
    const float* Wproj = (const float*)d_in[4];
    const float* bproj = (const float*)d_in[5];
    const float* W1    = (const float*)d_in[6];
    const float* b1    = (const float*)d_in[7];
    const float* W2    = (const float*)d_in[8];
    const float* b2    = (const float*)d_in[9];
    const float* ln1g  = (const float*)d_in[10];
    const float* ln1b  = (const float*)d_in[11];
    const float* ln2g  = (const float*)d_in[12];
    const float* ln2b  = (const float*)d_in[13];
    float* out = (float*)d_out;

    __half *h, *qkv, *ob, *ff, *wqkv, *wp, *w1, *w2;
    float *x1;
    cudaGetSymbolAddress((void**)&h,    g_h);
    cudaGetSymbolAddress((void**)&qkv,  g_qkv);
    cudaGetSymbolAddress((void**)&ob,   g_o);
    cudaGetSymbolAddress((void**)&x1,   g_x1);
    cudaGetSymbolAddress((void**)&ff,   g_ff);
    cudaGetSymbolAddress((void**)&wqkv, g_wqkv);
    cudaGetSymbolAddress((void**)&wp,   g_wp);
    cudaGetSymbolAddress((void**)&w1,   g_w1);
    cudaGetSymbolAddress((void**)&w2,   g_w2);

    cudaFuncSetAttribute(gemm_fp16, cudaFuncAttributeMaxDynamicSharedMemorySize, HG_SMEM);
    cudaFuncSetAttribute(attn_h,    cudaFuncAttributeMaxDynamicSharedMemorySize, ATTN_SMEM);

    dim3 tb(32, 8);

    // 1. LN1 -> half
    ln_kernel<<<M_, 256>>>(x, ln1g, ln1b, h);

    // 2. qkv weight repack
    repack_qkv3T<<<(C3_*C_)/256, 256>>>(Wq, Wk, Wv, wqkv);

    // 3. fused QKV projection -> half
    gemm_fp16<<<dim3(M_/128, C3_/128), 256, HG_SMEM>>>(h, wqkv, qkv, M_, C3_, C_,
                                                       nullptr, nullptr, 0, 2);

    // 4. fp16 causal flash attention -> half g_o   [ncu profile slot]
    dim3 ga(T_/128, H_, B_);
    attn_h<<<ga, 256, ATTN_SMEM>>>(qkv, ob);

    // 5. Wproj transpose
    transpose_h<<<dim3(C_/32,  C_/32),  tb>>>(Wproj, wp, C_,  C_);

    // 6. x1 = x + o @ Wproj + bproj  (fp32 out)
    gemm_fp16<<<dim3(M_/128, C_/128), 256, HG_SMEM>>>(ob, wp, x1, M_, C_, C_,
                                                      bproj, x, 0, 0);

    // 7. LN2 -> half
    ln_kernel<<<M_, 256>>>(x1, ln2g, ln2b, h);

    // 8. W1 transpose
    transpose_h<<<dim3(FF_/32, C_/32),  tb>>>(W1, w1, C_, FF_);

    // 9. ff = relu(h @ W1 + b1) -> half
    gemm_fp16<<<dim3(M_/128, FF_/128), 256, HG_SMEM>>>(h, w1, ff, M_, FF_, C_,
                                                       b1, nullptr, 1, 2);

    // 10. W2 transpose
    transpose_h<<<dim3(C_/32,  FF_/32), tb>>>(W2, w2, FF_, C_);

    // 11. out = x1 + ff @ W2 + b2  (final, fp32 out)
    gemm_fp16<<<dim3(M_/128, C_/128), 256, HG_SMEM>>>(ff, w2, out, M_, C_, FF_,
                                                      b2, x1, 0, 0);
}

// round 11
// speedup vs baseline: 1.4718x; 1.0777x over previous
#include <cuda_runtime.h>
#include <cuda_fp16.h>
#include <math.h>
#include <stdint.h>

// Problem constants
#define B_  4
#define T_  2048
#define C_  1024
#define C3_ 3072
#define H_  16
#define HS_ 64
#define FF_ 4096
#define M_  (B_*T_)     // 8192 rows
#define EPS_ 1e-5f

// ---------------- scratch (no dynamic alloc allowed) ----------------
__device__ __half g_h   [M_*C_];    // LN output (half)
__device__ __half g_qkv [M_*C3_];   // fused q|k|v (half), row stride 3072
__device__ __half g_o   [M_*C_];    // attention output (half)
__device__ float  g_x1  [M_*C_];    // x + attn_out @ Wproj + bproj (fp32)
__device__ __half g_ff  [M_*FF_];   // relu(h2 @ W1 + b1) (half)
__device__ __half g_wqkv[C3_*C_];   // repacked+transposed [3C, C] qkv weight (half)
__device__ __half g_wp  [C_*C_];    // transposed Wproj [N,K] (half)
__device__ __half g_w1  [FF_*C_];   // transposed W1 [4096,1024] (half)
__device__ __half g_w2  [C_*FF_];   // transposed W2 [1024,4096] (half)

__device__ __forceinline__ uint32_t f2tf32(float f) {
    uint32_t u;
    asm("cvt.rna.tf32.f32 %0, %1;" : "=r"(u) : "f"(f));
    return u;
}
__device__ __forceinline__ float roundtf(float f) {
    return __uint_as_float(f2tf32(f));
}

// fp16 mma
__device__ __forceinline__ void mma_fp16(float* c, const uint32_t* a, const uint32_t* b) {
    asm volatile("mma.sync.aligned.m16n8k16.row.col.f32.f16.f16.f32 "
        "{%0,%1,%2,%3}, {%4,%5,%6,%7}, {%8,%9}, {%0,%1,%2,%3};"
        : "+f"(c[0]), "+f"(c[1]), "+f"(c[2]), "+f"(c[3])
        : "r"(a[0]), "r"(a[1]), "r"(a[2]), "r"(a[3]), "r"(b[0]), "r"(b[1]));
}
__device__ __forceinline__ void mma_fp16_2(float* c, const uint32_t* a,
                                           uint32_t b0, uint32_t b1) {
    asm volatile("mma.sync.aligned.m16n8k16.row.col.f32.f16.f16.f32 "
        "{%0,%1,%2,%3}, {%4,%5,%6,%7}, {%8,%9}, {%0,%1,%2,%3};"
        : "+f"(c[0]), "+f"(c[1]), "+f"(c[2]), "+f"(c[3])
        : "r"(a[0]), "r"(a[1]), "r"(a[2]), "r"(a[3]), "r"(b0), "r"(b1));
}
__device__ __forceinline__ void ldm_x4(uint32_t* r, uint32_t addr) {
    asm volatile("ldmatrix.sync.aligned.m8n8.x4.shared.b16 {%0,%1,%2,%3}, [%4];"
        : "=r"(r[0]), "=r"(r[1]), "=r"(r[2]), "=r"(r[3]) : "r"(addr));
}
__device__ __forceinline__ void ldm_x4_t(uint32_t* r, uint32_t addr) {
    asm volatile("ldmatrix.sync.aligned.m8n8.x4.trans.shared.b16 {%0,%1,%2,%3}, [%4];"
        : "=r"(r[0]), "=r"(r[1]), "=r"(r[2]), "=r"(r[3]) : "r"(addr));
}
__device__ __forceinline__ uint32_t pack_h2(float lo, float hi) {
    __half2 h = __floats2half2_rn(lo, hi);
    return *reinterpret_cast<uint32_t*>(&h);
}
__device__ __forceinline__ uint32_t smem_u32(const void* p) {
    return (uint32_t)__cvta_generic_to_shared(p);
}

// ---------------- LayerNorm: fp32 in, half out ----------------
__global__ __launch_bounds__(256) void ln_kernel(const float* __restrict__ x,
                                                 const float* __restrict__ g,
                                                 const float* __restrict__ b,
                                                 __half* __restrict__ y)
{
    int row = blockIdx.x;
    const float* xr = x + (size_t)row * C_;
    __half* yr = y + (size_t)row * C_;
    int tid = threadIdx.x;

    float s = 0.f, s2 = 0.f;
    #pragma unroll
    for (int i = tid; i < C_; i += 256) {
        float v = xr[i];
        s += v; s2 += v * v;
    }
    __shared__ float rs[256], rs2[256];
    rs[tid] = s; rs2[tid] = s2;
    __syncthreads();
    for (int off = 128; off > 0; off >>= 1) {
        if (tid < off) { rs[tid] += rs[tid+off]; rs2[tid] += rs2[tid+off]; }
        __syncthreads();
    }
    float mean = rs[0] * (1.0f / C_);
    float var  = rs2[0] * (1.0f / C_) - mean * mean;
    float rstd = rsqrtf(var + EPS_);
    #pragma unroll
    for (int i = tid; i < C_; i += 256) {
        yr[i] = __float2half_rn((xr[i] - mean) * rstd * g[i] + b[i]);
    }
}

// ---------------- repack [H,C,HS]x3 -> [3C, C] half ----------------
__global__ void repack_qkv3T(const float* __restrict__ Wq,
                             const float* __restrict__ Wk,
                             const float* __restrict__ Wv,
                             __half* __restrict__ Wt)
{
    int idx = blockIdx.x * 256 + threadIdx.x;   // idx = n*C + c
    if (idx < C3_*C_) {
        int n = idx >> 10;
        int c = idx & (C_ - 1);
        int sec = n >> 10;
        int nn = n & (C_ - 1);
        int h = nn >> 6;
        int d = nn & (HS_ - 1);
        const float* W = (sec == 0) ? Wq : (sec == 1) ? Wk : Wv;
        Wt[idx] = __float2half_rn(W[(size_t)h * C_ * HS_ + (size_t)c * HS_ + d]);
    }
}

// ---------------- transpose to half: src [R, Cc] fp32 -> dst [Cc, R] half -------
__global__ void transpose_h(const float* __restrict__ S, __half* __restrict__ D,
                            int R, int Cc)
{
    __shared__ float t[32][33];
    int bx = blockIdx.x * 32, by = blockIdx.y * 32;
    int x = threadIdx.x, y = threadIdx.y;
    #pragma unroll
    for (int i = 0; i < 32; i += 8)
        t[y + i][x] = S[(size_t)(by + y + i) * Cc + bx + x];
    __syncthreads();
    #pragma unroll
    for (int i = 0; i < 32; i += 8)
        D[(size_t)(bx + y + i) * R + by + x] = __float2half_rn(t[x][y + i]);
}

// ---------------- fp16 mma.sync GEMM, BK=64, 2-stage ----------------
// C[M,N] = A[M,K] @ Bt[N,K]^T  (+bias)(+res)(relu)
// out_mode: 0 = fp32, 1 = fp32 tf32-rounded, 2 = half
// 128x128 CTA tile, BK=64 halves, 8 warps at 64x32, 2 CTA/SM.
// Stride 72 halves (36 words): ldmatrix phases hit banks 4r..4r+3 -> conflict-free.
#define HSTR 72
#define HG_STAGE (2*128*HSTR)          // halves per stage (A+B) = 18432
#define HG_SMEM  (2*HG_STAGE*2)        // 73728 bytes

__global__ __launch_bounds__(256, 2) void gemm_fp16(const __half* __restrict__ A,
                                                    const __half* __restrict__ Bt,
                                                    void* __restrict__ Cm,
                                                    int Mn, int Nn, int Kn,
                                                    const float* __restrict__ bias,
                                                    const float* __restrict__ res,
                                                    int relu, int out_mode)
{
    extern __shared__ __half smh[];
    const int tid = threadIdx.x;
    const int wid = tid >> 5, lane = tid & 31;
    const int g = lane >> 2, tg = lane & 3;
    const int warp_m = wid >> 2;       // 0..1  (64 rows)
    const int warp_n = wid & 3;        // 0..3  (32 cols)
    const int bm = blockIdx.x * 128;
    const int bn = blockIdx.y * 128;

    const int a_row  = lane & 15;
    const int a_koff = (lane >> 4) << 3;
    const int b_row  = ((lane >> 4) << 3) + (lane & 7);
    const int b_koff = ((lane >> 3) & 1) << 3;

    float acc[4][4][4];
    #pragma unroll
    for (int mi = 0; mi < 4; mi++)
        #pragma unroll
        for (int ni = 0; ni < 4; ni++)
            #pragma unroll
            for (int r = 0; r < 4; r++) acc[mi][ni][r] = 0.f;

    auto fill = [&](int s, int kt) {
        const int k0 = kt << 6;
        __half* As = smh + s * HG_STAGE;
        __half* Bs = As + 128 * HSTR;
        #pragma unroll
        for (int i = 0; i < 4; i++) {
            int idx = tid + (i << 8);          // 1024 chunks of 16B per matrix
            int r = idx >> 3, c8 = (idx & 7) << 3;
            uint32_t da = smem_u32(As + r * HSTR + c8);
            asm volatile("cp.async.cg.shared.global [%0], [%1], 16;"
                         :: "r"(da), "l"(A + (size_t)(bm + r) * Kn + k0 + c8));
            uint32_t db = smem_u32(Bs + r * HSTR + c8);
            asm volatile("cp.async.cg.shared.global [%0], [%1], 16;"
                         :: "r"(db), "l"(Bt + (size_t)(bn + r) * Kn + k0 + c8));
        }
        asm volatile("cp.async.commit_group;");
    };

    const int KT = Kn >> 6;
    fill(0, 0);

    for (int kt = 0; kt < KT; kt++) {
        asm volatile("cp.async.wait_group 0;");
        __syncthreads();
        if (kt + 1 < KT) fill((kt + 1) & 1, kt + 1);

        const __half* As = smh + (kt & 1) * HG_STAGE;
        const __half* Bs = As + 128 * HSTR;

        #pragma unroll
        for (int ks = 0; ks < 4; ks++) {
            const int kb0 = ks * 16;
            uint32_t af[4][4], bq[2][4];
            #pragma unroll
            for (int mi = 0; mi < 4; mi++)
                ldm_x4(af[mi], smem_u32(As + (warp_m * 64 + mi * 16 + a_row) * HSTR
                                           + kb0 + a_koff));
            #pragma unroll
            for (int np = 0; np < 2; np++)
                ldm_x4(bq[np], smem_u32(Bs + (warp_n * 32 + np * 16 + b_row) * HSTR
                                           + kb0 + b_koff));
            #pragma unroll
            for (int mi = 0; mi < 4; mi++)
                #pragma unroll
                for (int ni = 0; ni < 4; ni++)
                    mma_fp16(acc[mi][ni], af[mi], &bq[ni >> 1][(ni & 1) * 2]);
        }
        __syncthreads();
    }

    #pragma unroll
    for (int mi = 0; mi < 4; mi++) {
        #pragma unroll
        for (int ni = 0; ni < 4; ni++) {
            int row0 = bm + warp_m * 64 + mi * 16 + g;
            int col  = bn + warp_n * 32 + ni * 8 + tg * 2;
            float bx = 0.f, by = 0.f;
            if (bias) { bx = bias[col]; by = bias[col + 1]; }
            #pragma unroll
            for (int half_ = 0; half_ < 2; half_++) {
                int row = row0 + half_ * 8;
                float v0 = acc[mi][ni][half_ * 2 + 0] + bx;
                float v1 = acc[mi][ni][half_ * 2 + 1] + by;
                if (res) {
                    const float* rp = res + (size_t)row * Nn + col;
                    v0 += rp[0]; v1 += rp[1];
                }
                if (relu) { v0 = fmaxf(v0, 0.f); v1 = fmaxf(v1, 0.f); }
                if (out_mode == 2) {
                    __half2 hv = __floats2half2_rn(v0, v1);
                    *(__half2*)((__half*)Cm + (size_t)row * Nn + col) = hv;
                } else {
                    if (out_mode == 1) { v0 = roundtf(v0); v1 = roundtf(v1); }
                    *(float2*)((float*)Cm + (size_t)row * Nn + col) = make_float2(v0, v1);
                }
            }
        }
    }
}

// ---------------- fp16 tensor-core flash attention ----------------
// half qkv in, half out. 128 queries/block, 8 warps (m16), 64-key tiles.
// Softmax in exp2 domain: Q pre-scaled by log2(e)/8; bare exp2f in loop.
// Causal masking only on the (warp-uniform) diagonal tile.
#define AKSTR 72
#define AQSTR 72
#define ATTN_SMEM ((4*64*AKSTR + 128*AQSTR)*2)   // 55296 bytes

__global__ __launch_bounds__(256, 2) void attn_h(const __half* __restrict__ qkv,
                                                 __half* __restrict__ o)
{
    extern __shared__ __half smha[];
    __half* Ks = smha;                    // 2 stages 64 x AKSTR
    __half* Vs = smha + 2*64*AKSTR;       // 2 stages 64 x AKSTR
    __half* Qs = Vs + 2*64*AKSTR;         // 128 x AQSTR (Q, pre-scaled)

    const int tid = threadIdx.x, wid = tid >> 5, lane = tid & 31;
    const int g = lane >> 2, tg = lane & 3;
    const int qt0 = blockIdx.x * 128;
    const int h = blockIdx.y, b = blockIdx.z;

    const __half* qbase = qkv + (size_t)(b * T_ + qt0) * C3_ + h * HS_;
    const __half* kbase = qkv + (size_t)b * T_ * C3_ + C_  + h * HS_;
    const __half* vbase = qkv + (size_t)b * T_ * C3_ + 2*C_ + h * HS_;

    // stage Q tile (128x64 half), pre-scaled by log2(e)/8
    {
        int r = tid >> 1, c = (tid & 1) * 32;
        const __half2 s8 = __float2half2_rn(0.1803368801f);   // log2(e)/8
        #pragma unroll
        for (int i = 0; i < 4; i++) {
            __half2 v[4];
            *(uint4*)v = *(const uint4*)(qbase + (size_t)r * C3_ + c + i * 8);
            #pragma unroll
            for (int j = 0; j < 4; j++) v[j] = __hmul2(v[j], s8);
            *(uint4*)(Qs + r * AQSTR + c + i * 8) = *(uint4*)v;
        }
    }

    const int m0 = wid * 16;
    const int r0 = qt0 + m0 + g;
    const int my_max = qt0 + m0 + 15;
    const int ntiles = (qt0 + 128) >> 6;
    const int lrow = lane & 15;
    const int lcol = (lane >> 4) << 3;

    auto loadKV = [&](int s, int s0) {
        const __half* kp = kbase + (size_t)s0 * C3_;
        const __half* vp = vbase + (size_t)s0 * C3_;
        __half* Kd = Ks + s * 64 * AKSTR;
        __half* Vd = Vs + s * 64 * AKSTR;
        #pragma unroll
        for (int i = 0; i < 2; i++) {
            int idx = tid + (i << 8);           // 512 chunks of 16B per matrix
            int r = idx >> 3, c8 = (idx & 7) * 8;
            uint32_t dk = smem_u32(Kd + r * AKSTR + c8);
            asm volatile("cp.async.cg.shared.global [%0], [%1], 16;"
                         :: "r"(dk), "l"(kp + (size_t)r * C3_ + c8));
            uint32_t dv = smem_u32(Vd + r * AKSTR + c8);
            asm volatile("cp.async.cg.shared.global [%0], [%1], 16;"
                         :: "r"(dv), "l"(vp + (size_t)r * C3_ + c8));
        }
        asm volatile("cp.async.commit_group;");
    };

    loadKV(0, 0);
    __syncthreads();      // Q staging visible

    // Q fragments (registers, whole kernel)
    uint32_t qf[4][4];
    #pragma unroll
    for (int kc = 0; kc < 4; kc++)
        ldm_x4(qf[kc], smem_u32(Qs + (m0 + lrow) * AQSTR + kc * 16 + lcol));

    float mrow0 = -INFINITY, mrow1 = -INFINITY, lrow0s = 0.f, lrow1s = 0.f;
    float oacc[8][4];
    #pragma unroll
    for (int j = 0; j < 8; j++)
        #pragma unroll
        for (int r = 0; r < 4; r++) oacc[j][r] = 0.f;

    for (int t = 0; t < ntiles; t++) {
        const int s0 = t * 64;
        asm volatile("cp.async.wait_group 0;");
        __syncthreads();
        if (t + 1 < ntiles) loadKV((t + 1) & 1, s0 + 64);

        if (s0 <= my_max) {
            const __half* Kt = Ks + (t & 1) * 64 * AKSTR;
            const __half* Vt = Vs + (t & 1) * 64 * AKSTR;

            // S' = (Q*log2e/8) @ K^T  (scores in log2 domain)
            float sf[8][4];
            #pragma unroll
            for (int j = 0; j < 8; j++)
                #pragma unroll
                for (int r = 0; r < 4; r++) sf[j][r] = 0.f;
            #pragma unroll
            for (int kc = 0; kc < 4; kc++) {
                #pragma unroll
                for (int jb = 0; jb < 4; jb++) {
                    uint32_t kf[4];
                    ldm_x4(kf, smem_u32(Kt + (jb * 16 + lrow) * AKSTR + kc * 16 + lcol));
                    mma_fp16_2(sf[2*jb],   qf[kc], kf[0], kf[2]);
                    mma_fp16_2(sf[2*jb+1], qf[kc], kf[1], kf[3]);
                }
            }

            // causal mask only on the diagonal tile (warp-uniform branch)
            if (s0 + 63 > qt0 + m0) {
                #pragma unroll
                for (int j = 0; j < 8; j++) {
                    int c0 = s0 + j * 8 + 2 * tg, c1 = c0 + 1;
                    if (c0 > r0)     sf[j][0] = -INFINITY;
                    if (c1 > r0)     sf[j][1] = -INFINITY;
                    if (c0 > r0 + 8) sf[j][2] = -INFINITY;
                    if (c1 > r0 + 8) sf[j][3] = -INFINITY;
                }
            }

            float mx0 = -INFINITY, mx1 = -INFINITY;
            #pragma unroll
            for (int j = 0; j < 8; j++) {
                mx0 = fmaxf(mx0, fmaxf(sf[j][0], sf[j][1]));
                mx1 = fmaxf(mx1, fmaxf(sf[j][2], sf[j][3]));
            }
            mx0 = fmaxf(mx0, __shfl_xor_sync(0xffffffffu, mx0, 1));
            mx0 = fmaxf(mx0, __shfl_xor_sync(0xffffffffu, mx0, 2));
            mx1 = fmaxf(mx1, __shfl_xor_sync(0xffffffffu, mx1, 1));
            mx1 = fmaxf(mx1, __shfl_xor_sync(0xffffffffu, mx1, 2));

            float mn0 = fmaxf(mrow0, mx0), mn1 = fmaxf(mrow1, mx1);
            float corr0 = exp2f(mrow0 - mn0), corr1 = exp2f(mrow1 - mn1);
            float sum0 = 0.f, sum1 = 0.f;
            #pragma unroll
            for (int j = 0; j < 8; j++) {
                sf[j][0] = exp2f(sf[j][0] - mn0);
                sf[j][1] = exp2f(sf[j][1] - mn0);
                sf[j][2] = exp2f(sf[j][2] - mn1);
                sf[j][3] = exp2f(sf[j][3] - mn1);
                sum0 += sf[j][0] + sf[j][1];
                sum1 += sf[j][2] + sf[j][3];
            }
            sum0 += __shfl_xor_sync(0xffffffffu, sum0, 1);
            sum0 += __shfl_xor_sync(0xffffffffu, sum0, 2);
            sum1 += __shfl_xor_sync(0xffffffffu, sum1, 1);
            sum1 += __shfl_xor_sync(0xffffffffu, sum1, 2);
            lrow0s = lrow0s * corr0 + sum0;
            lrow1s = lrow1s * corr1 + sum1;
            mrow0 = mn0; mrow1 = mn1;
            #pragma unroll
            for (int j = 0; j < 8; j++) {
                oacc[j][0] *= corr0; oacc[j][1] *= corr0;
                oacc[j][2] *= corr1; oacc[j][3] *= corr1;
            }

            // O += P @ V : P A-frags packed in-register; V via ldmatrix.trans
            #pragma unroll
            for (int kk = 0; kk < 4; kk++) {
                uint32_t ap[4];
                ap[0] = pack_h2(sf[2*kk][0],   sf[2*kk][1]);
                ap[1] = pack_h2(sf[2*kk][2],   sf[2*kk][3]);
                ap[2] = pack_h2(sf[2*kk+1][0], sf[2*kk+1][1]);
                ap[3] = pack_h2(sf[2*kk+1][2], sf[2*kk+1][3]);
                #pragma unroll
                for (int db = 0; db < 4; db++) {
                    uint32_t vf[4];
                    ldm_x4_t(vf, smem_u32(Vt + (kk * 16 + lrow) * AKSTR + db * 16 + lcol));
                    mma_fp16_2(oacc[2*db],   ap, vf[0], vf[1]);
                    mma_fp16_2(oacc[2*db+1], ap, vf[2], vf[3]);
                }
            }
        }
    }

    // epilogue: normalize, write half (feeds proj GEMM)
    float inv0 = 1.f / lrow0s;
    float inv1 = 1.f / lrow1s;
    __half* ob0 = o + ((size_t)(b * T_ + r0)) * C_ + h * HS_;
    __half* ob1 = ob0 + (size_t)8 * C_;
    #pragma unroll
    for (int j = 0; j < 8; j++) {
        int col = j * 8 + 2 * tg;
        *(__half2*)(ob0 + col) = __floats2half2_rn(oacc[j][0] * inv0, oacc[j][1] * inv0);
        *(__half2*)(ob1 + col) = __floats2half2_rn(oacc[j][2] * inv1, oacc[j][3] * inv1);
    }
}

// ---------------- launch ----------------
extern "C" void kernel_launch(void* const* d_in, const int* in_sizes, int n_in,
                              void* d_out, int out_size)
{
    const float* x     = (const float*)d_in[0];
    const float* Wq    = (const float*)d_in[1];
    const float* Wk    = (const float*)d_in[2];
    const float* Wv    = (const float*)d_in[3];
    const float* Wproj = (const float*)d_in[4];
    const float* bproj = (const float*)d_in[5];
    const float* W1    = (const float*)d_in[6];
    const float* b1    = (const float*)d_in[7];
    const float* W2    = (const float*)d_in[8];
    const float* b2    = (const float*)d_in[9];
    const float* ln1g  = (const float*)d_in[10];
    const float* ln1b  = (const float*)d_in[11];
    const float* ln2g  = (const float*)d_in[12];
    const float* ln2b  = (const float*)d_in[13];
    float* out = (float*)d_out;

    __half *h, *qkv, *ob, *ff, *wqkv, *wp, *w1, *w2;
    float *x1;
    cudaGetSymbolAddress((void**)&h,    g_h);
    cudaGetSymbolAddress((void**)&qkv,  g_qkv);
    cudaGetSymbolAddress((void**)&ob,   g_o);
    cudaGetSymbolAddress((void**)&x1,   g_x1);
    cudaGetSymbolAddress((void**)&ff,   g_ff);
    cudaGetSymbolAddress((void**)&wqkv, g_wqkv);
    cudaGetSymbolAddress((void**)&wp,   g_wp);
    cudaGetSymbolAddress((void**)&w1,   g_w1);
    cudaGetSymbolAddress((void**)&w2,   g_w2);

    cudaFuncSetAttribute(gemm_fp16, cudaFuncAttributeMaxDynamicSharedMemorySize, HG_SMEM);
    cudaFuncSetAttribute(attn_h,    cudaFuncAttributeMaxDynamicSharedMemorySize, ATTN_SMEM);

    dim3 tb(32, 8);

    // 1. LN1 -> half
    ln_kernel<<<M_, 256>>>(x, ln1g, ln1b, h);

    // 2. qkv weight repack
    repack_qkv3T<<<(C3_*C_)/256, 256>>>(Wq, Wk, Wv, wqkv);

    // 3. fused QKV projection -> half
    gemm_fp16<<<dim3(M_/128, C3_/128), 256, HG_SMEM>>>(h, wqkv, qkv, M_, C3_, C_,
                                                       nullptr, nullptr, 0, 2);

    // 4. fp16 causal flash attention -> half g_o   [ncu profile slot]
    dim3 ga(T_/128, H_, B_);
    attn_h<<<ga, 256, ATTN_SMEM>>>(qkv, ob);

    // 5. Wproj transpose
    transpose_h<<<dim3(C_/32,  C_/32),  tb>>>(Wproj, wp, C_,  C_);

    // 6. x1 = x + o @ Wproj + bproj  (fp32 out)
    gemm_fp16<<<dim3(M_/128, C_/128), 256, HG_SMEM>>>(ob, wp, x1, M_, C_, C_,
                                                      bproj, x, 0, 0);

    // 7. LN2 -> half
    ln_kernel<<<M_, 256>>>(x1, ln2g, ln2b, h);

    // 8. W1 transpose
    transpose_h<<<dim3(FF_/32, C_/32),  tb>>>(W1, w1, C_, FF_);

    // 9. ff = relu(h @ W1 + b1) -> half
    gemm_fp16<<<dim3(M_/128, FF_/128), 256, HG_SMEM>>>(h, w1, ff, M_, FF_, C_,
                                                       b1, nullptr, 1, 2);

    // 10. W2 transpose
    transpose_h<<<dim3(C_/32,  FF_/32), tb>>>(W2, w2, FF_, C_);

    // 11. out = x1 + ff @ W2 + b2  (final, fp32 out)
    gemm_fp16<<<dim3(M_/128, C_/128), 256, HG_SMEM>>>(ff, w2, out, M_, C_, FF_,
                                                      b2, x1, 0, 0);
}

// round 12
// speedup vs baseline: 1.5007x; 1.0196x over previous
#include <cuda_runtime.h>
#include <cuda_fp16.h>
#include <math.h>
#include <stdint.h>

// Problem constants
#define B_  4
#define T_  2048
#define C_  1024
#define C3_ 3072
#define H_  16
#define HS_ 64
#define FF_ 4096
#define M_  (B_*T_)     // 8192 rows
#define EPS_ 1e-5f

// ---------------- scratch (no dynamic alloc allowed) ----------------
__device__ __half g_h   [M_*C_];    // LN output (half)
__device__ __half g_qkv [M_*C3_];   // fused q|k|v (half), row stride 3072
__device__ __half g_o   [M_*C_];    // attention output (half)
__device__ float  g_x1  [M_*C_];    // x + attn_out @ Wproj + bproj (fp32)
__device__ __half g_ff  [M_*FF_];   // relu(h2 @ W1 + b1) (half)
__device__ __half g_wqkv[C3_*C_];   // repacked+transposed [3C, C] qkv weight (half)
__device__ __half g_wp  [C_*C_];    // transposed Wproj [N,K] (half)
__device__ __half g_w1  [FF_*C_];   // transposed W1 [4096,1024] (half)
__device__ __half g_w2  [C_*FF_];   // transposed W2 [1024,4096] (half)

__device__ __forceinline__ uint32_t f2tf32(float f) {
    uint32_t u;
    asm("cvt.rna.tf32.f32 %0, %1;" : "=r"(u) : "f"(f));
    return u;
}
__device__ __forceinline__ float roundtf(float f) {
    return __uint_as_float(f2tf32(f));
}

// fp16 mma
__device__ __forceinline__ void mma_fp16(float* c, const uint32_t* a, const uint32_t* b) {
    asm volatile("mma.sync.aligned.m16n8k16.row.col.f32.f16.f16.f32 "
        "{%0,%1,%2,%3}, {%4,%5,%6,%7}, {%8,%9}, {%0,%1,%2,%3};"
        : "+f"(c[0]), "+f"(c[1]), "+f"(c[2]), "+f"(c[3])
        : "r"(a[0]), "r"(a[1]), "r"(a[2]), "r"(a[3]), "r"(b[0]), "r"(b[1]));
}
__device__ __forceinline__ void mma_fp16_2(float* c, const uint32_t* a,
                                           uint32_t b0, uint32_t b1) {
    asm volatile("mma.sync.aligned.m16n8k16.row.col.f32.f16.f16.f32 "
        "{%0,%1,%2,%3}, {%4,%5,%6,%7}, {%8,%9}, {%0,%1,%2,%3};"
        : "+f"(c[0]), "+f"(c[1]), "+f"(c[2]), "+f"(c[3])
        : "r"(a[0]), "r"(a[1]), "r"(a[2]), "r"(a[3]), "r"(b0), "r"(b1));
}
__device__ __forceinline__ void ldm_x4(uint32_t* r, uint32_t addr) {
    asm volatile("ldmatrix.sync.aligned.m8n8.x4.shared.b16 {%0,%1,%2,%3}, [%4];"
        : "=r"(r[0]), "=r"(r[1]), "=r"(r[2]), "=r"(r[3]) : "r"(addr));
}
__device__ __forceinline__ void ldm_x4_t(uint32_t* r, uint32_t addr) {
    asm volatile("ldmatrix.sync.aligned.m8n8.x4.trans.shared.b16 {%0,%1,%2,%3}, [%4];"
        : "=r"(r[0]), "=r"(r[1]), "=r"(r[2]), "=r"(r[3]) : "r"(addr));
}
__device__ __forceinline__ uint32_t smem_u32(const void* p) {
    return (uint32_t)__cvta_generic_to_shared(p);
}

// ---------------- LayerNorm: fp32 in, half out ----------------
__global__ __launch_bounds__(256) void ln_kernel(const float* __restrict__ x,
                                                 const float* __restrict__ g,
                                                 const float* __restrict__ b,
                                                 __half* __restrict__ y)
{
    int row = blockIdx.x;
    const float* xr = x + (size_t)row * C_;
    __half* yr = y + (size_t)row * C_;
    int tid = threadIdx.x;

    float s = 0.f, s2 = 0.f;
    #pragma unroll
    for (int i = tid; i < C_; i += 256) {
        float v = xr[i];
        s += v; s2 += v * v;
    }
    __shared__ float rs[256], rs2[256];
    rs[tid] = s; rs2[tid] = s2;
    __syncthreads();
    for (int off = 128; off > 0; off >>= 1) {
        if (tid < off) { rs[tid] += rs[tid+off]; rs2[tid] += rs2[tid+off]; }
        __syncthreads();
    }
    float mean = rs[0] * (1.0f / C_);
    float var  = rs2[0] * (1.0f / C_) - mean * mean;
    float rstd = rsqrtf(var + EPS_);
    #pragma unroll
    for (int i = tid; i < C_; i += 256) {
        yr[i] = __float2half_rn((xr[i] - mean) * rstd * g[i] + b[i]);
    }
}

// ---------------- repack [H,C,HS]x3 -> [3C, C] half ----------------
__global__ void repack_qkv3T(const float* __restrict__ Wq,
                             const float* __restrict__ Wk,
                             const float* __restrict__ Wv,
                             __half* __restrict__ Wt)
{
    int idx = blockIdx.x * 256 + threadIdx.x;   // idx = n*C + c
    if (idx < C3_*C_) {
        int n = idx >> 10;
        int c = idx & (C_ - 1);
        int sec = n >> 10;
        int nn = n & (C_ - 1);
        int h = nn >> 6;
        int d = nn & (HS_ - 1);
        const float* W = (sec == 0) ? Wq : (sec == 1) ? Wk : Wv;
        Wt[idx] = __float2half_rn(W[(size_t)h * C_ * HS_ + (size_t)c * HS_ + d]);
    }
}

// ---------------- transpose to half: src [R, Cc] fp32 -> dst [Cc, R] half -------
__global__ void transpose_h(const float* __restrict__ S, __half* __restrict__ D,
                            int R, int Cc)
{
    __shared__ float t[32][33];
    int bx = blockIdx.x * 32, by = blockIdx.y * 32;
    int x = threadIdx.x, y = threadIdx.y;
    #pragma unroll
    for (int i = 0; i < 32; i += 8)
        t[y + i][x] = S[(size_t)(by + y + i) * Cc + bx + x];
    __syncthreads();
    #pragma unroll
    for (int i = 0; i < 32; i += 8)
        D[(size_t)(bx + y + i) * R + by + x] = __float2half_rn(t[x][y + i]);
}

// ---------------- fp16 mma.sync GEMM, BK=64, 2-stage ----------------
// C[M,N] = A[M,K] @ Bt[N,K]^T  (+bias)(+res)(relu)
// out_mode: 0 = fp32, 1 = fp32 tf32-rounded, 2 = half
// 128x128 CTA tile, BK=64 halves, 8 warps at 64x32, 2 CTA/SM.
#define HSTR 72
#define HG_STAGE (2*128*HSTR)          // halves per stage (A+B) = 18432
#define HG_SMEM  (2*HG_STAGE*2)        // 73728 bytes

__global__ __launch_bounds__(256, 2) void gemm_fp16(const __half* __restrict__ A,
                                                    const __half* __restrict__ Bt,
                                                    void* __restrict__ Cm,
                                                    int Mn, int Nn, int Kn,
                                                    const float* __restrict__ bias,
                                                    const float* __restrict__ res,
                                                    int relu, int out_mode)
{
    extern __shared__ __half smh[];
    const int tid = threadIdx.x;
    const int wid = tid >> 5, lane = tid & 31;
    const int g = lane >> 2, tg = lane & 3;
    const int warp_m = wid >> 2;       // 0..1  (64 rows)
    const int warp_n = wid & 3;        // 0..3  (32 cols)
    const int bm = blockIdx.x * 128;
    const int bn = blockIdx.y * 128;

    const int a_row  = lane & 15;
    const int a_koff = (lane >> 4) << 3;
    const int b_row  = ((lane >> 4) << 3) + (lane & 7);
    const int b_koff = ((lane >> 3) & 1) << 3;

    float acc[4][4][4];
    #pragma unroll
    for (int mi = 0; mi < 4; mi++)
        #pragma unroll
        for (int ni = 0; ni < 4; ni++)
            #pragma unroll
            for (int r = 0; r < 4; r++) acc[mi][ni][r] = 0.f;

    auto fill = [&](int s, int kt) {
        const int k0 = kt << 6;
        __half* As = smh + s * HG_STAGE;
        __half* Bs = As + 128 * HSTR;
        #pragma unroll
        for (int i = 0; i < 4; i++) {
            int idx = tid + (i << 8);          // 1024 chunks of 16B per matrix
            int r = idx >> 3, c8 = (idx & 7) << 3;
            uint32_t da = smem_u32(As + r * HSTR + c8);
            asm volatile("cp.async.cg.shared.global [%0], [%1], 16;"
                         :: "r"(da), "l"(A + (size_t)(bm + r) * Kn + k0 + c8));
            uint32_t db = smem_u32(Bs + r * HSTR + c8);
            asm volatile("cp.async.cg.shared.global [%0], [%1], 16;"
                         :: "r"(db), "l"(Bt + (size_t)(bn + r) * Kn + k0 + c8));
        }
        asm volatile("cp.async.commit_group;");
    };

    const int KT = Kn >> 6;
    fill(0, 0);

    for (int kt = 0; kt < KT; kt++) {
        asm volatile("cp.async.wait_group 0;");
        __syncthreads();
        if (kt + 1 < KT) fill((kt + 1) & 1, kt + 1);

        const __half* As = smh + (kt & 1) * HG_STAGE;
        const __half* Bs = As + 128 * HSTR;

        #pragma unroll
        for (int ks = 0; ks < 4; ks++) {
            const int kb0 = ks * 16;
            uint32_t af[4][4], bq[2][4];
            #pragma unroll
            for (int mi = 0; mi < 4; mi++)
                ldm_x4(af[mi], smem_u32(As + (warp_m * 64 + mi * 16 + a_row) * HSTR
                                           + kb0 + a_koff));
            #pragma unroll
            for (int np = 0; np < 2; np++)
                ldm_x4(bq[np], smem_u32(Bs + (warp_n * 32 + np * 16 + b_row) * HSTR
                                           + kb0 + b_koff));
            #pragma unroll
            for (int mi = 0; mi < 4; mi++)
                #pragma unroll
                for (int ni = 0; ni < 4; ni++)
                    mma_fp16(acc[mi][ni], af[mi], &bq[ni >> 1][(ni & 1) * 2]);
        }
        // no trailing sync: next iteration's top __syncthreads orders
        // this compute before fill(kt+2) overwrites this stage.
    }

    #pragma unroll
    for (int mi = 0; mi < 4; mi++) {
        #pragma unroll
        for (int ni = 0; ni < 4; ni++) {
            int row0 = bm + warp_m * 64 + mi * 16 + g;
            int col  = bn + warp_n * 32 + ni * 8 + tg * 2;
            float bx = 0.f, by = 0.f;
            if (bias) { bx = bias[col]; by = bias[col + 1]; }
            #pragma unroll
            for (int half_ = 0; half_ < 2; half_++) {
                int row = row0 + half_ * 8;
                float v0 = acc[mi][ni][half_ * 2 + 0] + bx;
                float v1 = acc[mi][ni][half_ * 2 + 1] + by;
                if (res) {
                    const float* rp = res + (size_t)row * Nn + col;
                    v0 += rp[0]; v1 += rp[1];
                }
                if (relu) { v0 = fmaxf(v0, 0.f); v1 = fmaxf(v1, 0.f); }
                if (out_mode == 2) {
                    __half2 hv = __floats2half2_rn(v0, v1);
                    *(__half2*)((__half*)Cm + (size_t)row * Nn + col) = hv;
                } else {
                    if (out_mode == 1) { v0 = roundtf(v0); v1 = roundtf(v1); }
                    *(float2*)((float*)Cm + (size_t)row * Nn + col) = make_float2(v0, v1);
                }
            }
        }
    }
}

// ---------------- fp16 tensor-core flash attention ----------------
// half qkv in, half out. 128 queries/block, 8 warps (m16), 64-key tiles.
// Softmax in exp2 domain (Q pre-scaled by log2(e)/8); exponentials via
// h2exp2 on packed fp16 pairs; row sums via ones-matrix MMA (no shuffles).
#define AKSTR 72
#define AQSTR 72
#define ATTN_SMEM ((4*64*AKSTR + 128*AQSTR)*2)   // 55296 bytes

__global__ __launch_bounds__(256, 2) void attn_h(const __half* __restrict__ qkv,
                                                 __half* __restrict__ o)
{
    extern __shared__ __half smha[];
    __half* Ks = smha;                    // 2 stages 64 x AKSTR
    __half* Vs = smha + 2*64*AKSTR;       // 2 stages 64 x AKSTR
    __half* Qs = Vs + 2*64*AKSTR;         // 128 x AQSTR (Q, pre-scaled)

    const int tid = threadIdx.x, wid = tid >> 5, lane = tid & 31;
    const int g = lane >> 2, tg = lane & 3;
    const int qt0 = blockIdx.x * 128;
    const int h = blockIdx.y, b = blockIdx.z;

    const __half* qbase = qkv + (size_t)(b * T_ + qt0) * C3_ + h * HS_;
    const __half* kbase = qkv + (size_t)b * T_ * C3_ + C_  + h * HS_;
    const __half* vbase = qkv + (size_t)b * T_ * C3_ + 2*C_ + h * HS_;

    // stage Q tile (128x64 half), pre-scaled by log2(e)/8
    {
        int r = tid >> 1, c = (tid & 1) * 32;
        const __half2 s8 = __float2half2_rn(0.1803368801f);   // log2(e)/8
        #pragma unroll
        for (int i = 0; i < 4; i++) {
            __half2 v[4];
            *(uint4*)v = *(const uint4*)(qbase + (size_t)r * C3_ + c + i * 8);
            #pragma unroll
            for (int j = 0; j < 4; j++) v[j] = __hmul2(v[j], s8);
            *(uint4*)(Qs + r * AQSTR + c + i * 8) = *(uint4*)v;
        }
    }

    const int m0 = wid * 16;
    const int r0 = qt0 + m0 + g;
    const int my_max = qt0 + m0 + 15;
    const int ntiles = (qt0 + 128) >> 6;
    const int lrow = lane & 15;
    const int lcol = (lane >> 4) << 3;
    const uint32_t ONE2 = 0x3C003C00u;    // half2(1, 1)

    auto loadKV = [&](int s, int s0) {
        const __half* kp = kbase + (size_t)s0 * C3_;
        const __half* vp = vbase + (size_t)s0 * C3_;
        __half* Kd = Ks + s * 64 * AKSTR;
        __half* Vd = Vs + s * 64 * AKSTR;
        #pragma unroll
        for (int i = 0; i < 2; i++) {
            int idx = tid + (i << 8);           // 512 chunks of 16B per matrix
            int r = idx >> 3, c8 = (idx & 7) * 8;
            uint32_t dk = smem_u32(Kd + r * AKSTR + c8);
            asm volatile("cp.async.cg.shared.global [%0], [%1], 16;"
                         :: "r"(dk), "l"(kp + (size_t)r * C3_ + c8));
            uint32_t dv = smem_u32(Vd + r * AKSTR + c8);
            asm volatile("cp.async.cg.shared.global [%0], [%1], 16;"
                         :: "r"(dv), "l"(vp + (size_t)r * C3_ + c8));
        }
        asm volatile("cp.async.commit_group;");
    };

    loadKV(0, 0);
    __syncthreads();      // Q staging visible

    // Q fragments (registers, whole kernel)
    uint32_t qf[4][4];
    #pragma unroll
    for (int kc = 0; kc < 4; kc++)
        ldm_x4(qf[kc], smem_u32(Qs + (m0 + lrow) * AQSTR + kc * 16 + lcol));

    float mrow0 = -INFINITY, mrow1 = -INFINITY, lrow0s = 0.f, lrow1s = 0.f;
    float oacc[8][4];
    #pragma unroll
    for (int j = 0; j < 8; j++)
        #pragma unroll
        for (int r = 0; r < 4; r++) oacc[j][r] = 0.f;

    for (int t = 0; t < ntiles; t++) {
        const int s0 = t * 64;
        asm volatile("cp.async.wait_group 0;");
        __syncthreads();
        if (t + 1 < ntiles) loadKV((t + 1) & 1, s0 + 64);

        if (s0 <= my_max) {
            const __half* Kt = Ks + (t & 1) * 64 * AKSTR;
            const __half* Vt = Vs + (t & 1) * 64 * AKSTR;

            // S' = (Q*log2e/8) @ K^T  (scores in log2 domain)
            float sf[8][4];
            #pragma unroll
            for (int j = 0; j < 8; j++)
                #pragma unroll
                for (int r = 0; r < 4; r++) sf[j][r] = 0.f;
            #pragma unroll
            for (int kc = 0; kc < 4; kc++) {
                #pragma unroll
                for (int jb = 0; jb < 4; jb++) {
                    uint32_t kf[4];
                    ldm_x4(kf, smem_u32(Kt + (jb * 16 + lrow) * AKSTR + kc * 16 + lcol));
                    mma_fp16_2(sf[2*jb],   qf[kc], kf[0], kf[2]);
                    mma_fp16_2(sf[2*jb+1], qf[kc], kf[1], kf[3]);
                }
            }

            // causal mask only on the diagonal tile (warp-uniform branch)
            if (s0 + 63 > qt0 + m0) {
                #pragma unroll
                for (int j = 0; j < 8; j++) {
                    int c0 = s0 + j * 8 + 2 * tg, c1 = c0 + 1;
                    if (c0 > r0)     sf[j][0] = -INFINITY;
                    if (c1 > r0)     sf[j][1] = -INFINITY;
                    if (c0 > r0 + 8) sf[j][2] = -INFINITY;
                    if (c1 > r0 + 8) sf[j][3] = -INFINITY;
                }
            }

            float mx0 = -INFINITY, mx1 = -INFINITY;
            #pragma unroll
            for (int j = 0; j < 8; j++) {
                mx0 = fmaxf(mx0, fmaxf(sf[j][0], sf[j][1]));
                mx1 = fmaxf(mx1, fmaxf(sf[j][2], sf[j][3]));
            }
            mx0 = fmaxf(mx0, __shfl_xor_sync(0xffffffffu, mx0, 1));
            mx0 = fmaxf(mx0, __shfl_xor_sync(0xffffffffu, mx0, 2));
            mx1 = fmaxf(mx1, __shfl_xor_sync(0xffffffffu, mx1, 1));
            mx1 = fmaxf(mx1, __shfl_xor_sync(0xffffffffu, mx1, 2));

            float mn0 = fmaxf(mrow0, mx0), mn1 = fmaxf(mrow1, mx1);
            float corr0 = exp2f(mrow0 - mn0), corr1 = exp2f(mrow1 - mn1);
            mrow0 = mn0; mrow1 = mn1;

            // P = exp2(S' - m) computed directly in fp16 pairs (A-frag words)
            uint32_t pj[8][2];
            #pragma unroll
            for (int j = 0; j < 8; j++) {
                __half2 e0 = h2exp2(__floats2half2_rn(sf[j][0] - mn0, sf[j][1] - mn0));
                __half2 e1 = h2exp2(__floats2half2_rn(sf[j][2] - mn1, sf[j][3] - mn1));
                pj[j][0] = *reinterpret_cast<uint32_t*>(&e0);
                pj[j][1] = *reinterpret_cast<uint32_t*>(&e1);
            }

            // rescale running output
            #pragma unroll
            for (int j = 0; j < 8; j++) {
                oacc[j][0] *= corr0; oacc[j][1] *= corr0;
                oacc[j][2] *= corr1; oacc[j][3] *= corr1;
            }

            // O += P @ V  and  l += P @ ones  (row sums via MMA, no shuffles)
            float lacc[4] = {0.f, 0.f, 0.f, 0.f};
            #pragma unroll
            for (int kk = 0; kk < 4; kk++) {
                uint32_t ap[4] = { pj[2*kk][0], pj[2*kk][1],
                                   pj[2*kk+1][0], pj[2*kk+1][1] };
                mma_fp16_2(lacc, ap, ONE2, ONE2);
                #pragma unroll
                for (int db = 0; db < 4; db++) {
                    uint32_t vf[4];
                    ldm_x4_t(vf, smem_u32(Vt + (kk * 16 + lrow) * AKSTR + db * 16 + lcol));
                    mma_fp16_2(oacc[2*db],   ap, vf[0], vf[1]);
                    mma_fp16_2(oacc[2*db+1], ap, vf[2], vf[3]);
                }
            }
            lrow0s = lrow0s * corr0 + lacc[0];
            lrow1s = lrow1s * corr1 + lacc[2];
        }
    }

    // epilogue: normalize, write half (feeds proj GEMM)
    float inv0 = 1.f / lrow0s;
    float inv1 = 1.f / lrow1s;
    __half* ob0 = o + ((size_t)(b * T_ + r0)) * C_ + h * HS_;
    __half* ob1 = ob0 + (size_t)8 * C_;
    #pragma unroll
    for (int j = 0; j < 8; j++) {
        int col = j * 8 + 2 * tg;
        *(__half2*)(ob0 + col) = __floats2half2_rn(oacc[j][0] * inv0, oacc[j][1] * inv0);
        *(__half2*)(ob1 + col) = __floats2half2_rn(oacc[j][2] * inv1, oacc[j][3] * inv1);
    }
}

// ---------------- launch ----------------
extern "C" void kernel_launch(void* const* d_in, const int* in_sizes, int n_in,
                              void* d_out, int out_size)
{
    const float* x     = (const float*)d_in[0];
    const float* Wq    = (const float*)d_in[1];
    const float* Wk    = (const float*)d_in[2];
    const float* Wv    = (const float*)d_in[3];
    const float* Wproj = (const float*)d_in[4];
    const float* bproj = (const float*)d_in[5];
    const float* W1    = (const float*)d_in[6];
    const float* b1    = (const float*)d_in[7];
    const float* W2    = (const float*)d_in[8];
    const float* b2    = (const float*)d_in[9];
    const float* ln1g  = (const float*)d_in[10];
    const float* ln1b  = (const float*)d_in[11];
    const float* ln2g  = (const float*)d_in[12];
    const float* ln2b  = (const float*)d_in[13];
    float* out = (float*)d_out;

    __half *h, *qkv, *ob, *ff, *wqkv, *wp, *w1, *w2;
    float *x1;
    cudaGetSymbolAddress((void**)&h,    g_h);
    cudaGetSymbolAddress((void**)&qkv,  g_qkv);
    cudaGetSymbolAddress((void**)&ob,   g_o);
    cudaGetSymbolAddress((void**)&x1,   g_x1);
    cudaGetSymbolAddress((void**)&ff,   g_ff);
    cudaGetSymbolAddress((void**)&wqkv, g_wqkv);
    cudaGetSymbolAddress((void**)&wp,   g_wp);
    cudaGetSymbolAddress((void**)&w1,   g_w1);
    cudaGetSymbolAddress((void**)&w2,   g_w2);

    cudaFuncSetAttribute(gemm_fp16, cudaFuncAttributeMaxDynamicSharedMemorySize, HG_SMEM);
    cudaFuncSetAttribute(attn_h,    cudaFuncAttributeMaxDynamicSharedMemorySize, ATTN_SMEM);

    dim3 tb(32, 8);

    // 1. LN1 -> half
    ln_kernel<<<M_, 256>>>(x, ln1g, ln1b, h);

    // 2. qkv weight repack
    repack_qkv3T<<<(C3_*C_)/256, 256>>>(Wq, Wk, Wv, wqkv);

    // 3. fused QKV projection -> half
    gemm_fp16<<<dim3(M_/128, C3_/128), 256, HG_SMEM>>>(h, wqkv, qkv, M_, C3_, C_,
                                                       nullptr, nullptr, 0, 2);

    // 4. fp16 causal flash attention -> half g_o   [ncu profile slot]
    dim3 ga(T_/128, H_, B_);
    attn_h<<<ga, 256, ATTN_SMEM>>>(qkv, ob);

    // 5. Wproj transpose
    transpose_h<<<dim3(C_/32,  C_/32),  tb>>>(Wproj, wp, C_,  C_);

    // 6. x1 = x + o @ Wproj + bproj  (fp32 out)
    gemm_fp16<<<dim3(M_/128, C_/128), 256, HG_SMEM>>>(ob, wp, x1, M_, C_, C_,
                                                      bproj, x, 0, 0);

    // 7. LN2 -> half
    ln_kernel<<<M_, 256>>>(x1, ln2g, ln2b, h);

    // 8. W1 transpose
    transpose_h<<<dim3(FF_/32, C_/32),  tb>>>(W1, w1, C_, FF_);

    // 9. ff = relu(h @ W1 + b1) -> half
    gemm_fp16<<<dim3(M_/128, FF_/128), 256, HG_SMEM>>>(h, w1, ff, M_, FF_, C_,
                                                       b1, nullptr, 1, 2);

    // 10. W2 transpose
    transpose_h<<<dim3(C_/32,  FF_/32), tb>>>(W2, w2, FF_, C_);

    // 11. out = x1 + ff @ W2 + b2  (final, fp32 out)
    gemm_fp16<<<dim3(M_/128, C_/128), 256, HG_SMEM>>>(ff, w2, out, M_, C_, FF_,
                                                      b2, x1, 0, 0);
}